// round 15
// baseline (speedup 1.0000x reference)
#include <cuda_runtime.h>
#include <cuda_fp16.h>
#include <math.h>
#include <stdint.h>

#define TOKENS   131072
#define CDIM     256
#define QKVDIM   768
#define HIDDIM   512

// ---------------- scratch ----------------
__device__ __half g_qkv16[100663296];  // (131072, 768) fp16
__device__ float  g_y    [33554432];   // (131072, 256) fp32
__device__ __half g_xw16 [33554432];   // (131072, 256) fp16
__device__ __half g_attn16[33554432];  // (131072, 256) fp16 (window layout)
__device__ __half g_btq  [196608];     // [768,256]  = [wq*scale | wkv]^T
__device__ __half g_btp  [65536];      // [256,256]  = wp^T
__device__ __half g_bt1  [131072];     // [512,256]  = w1^T
__device__ __half g_bt2  [131072];     // [256,512]  = w2^T

// ---------------- helpers ----------------
__device__ __forceinline__ uint32_t smem_u32(const void* p) {
    uint32_t a;
    asm("{ .reg .u64 t; cvta.to.shared.u64 t, %1; cvt.u32.u64 %0, t; }" : "=r"(a) : "l"(p));
    return a;
}
__device__ __forceinline__ float gelu_exact(float x) {
    return 0.5f * x * (1.0f + erff(x * 0.70710678118654752f));
}
#define MMA_161608(ACC, A0,A1,A2,A3, B0,B1) \
    asm volatile( \
        "mma.sync.aligned.m16n8k16.row.col.f32.f16.f16.f32 " \
        "{%0,%1,%2,%3}, {%4,%5,%6,%7}, {%8,%9}, {%0,%1,%2,%3};" \
        : "+f"((ACC)[0]), "+f"((ACC)[1]), "+f"((ACC)[2]), "+f"((ACC)[3]) \
        : "r"(A0), "r"(A1), "r"(A2), "r"(A3), "r"(B0), "r"(B1))
#define CP_ASYNC16(dst, src) \
    asm volatile("cp.async.cg.shared.global [%0], [%1], 16;" :: "r"(dst), "l"(src))
#define CP_COMMIT() asm volatile("cp.async.commit_group;")
#define CP_WAIT0()  asm volatile("cp.async.wait_group 0;" ::: "memory")
#define LDM_X4(R0,R1,R2,R3,AD) \
    asm volatile("ldmatrix.sync.aligned.m8n8.x4.shared.b16 {%0,%1,%2,%3}, [%4];" \
                 : "=r"(R0), "=r"(R1), "=r"(R2), "=r"(R3) : "r"(AD))

// ---------------- weight prep ----------------
__global__ void prep_w_kernel(const float* __restrict__ wq, const float* __restrict__ wkv,
                              const float* __restrict__ wp, const float* __restrict__ w1,
                              const float* __restrict__ w2) {
    const float scale = 0.17677669529663687f;
    int idx = blockIdx.x * 256 + threadIdx.x;   // 524288 total
    if (idx < 196608) {
        int n = idx / 256, k = idx % 256;
        float v = (n < 256) ? wq[k * 256 + n] * scale : wkv[k * 512 + (n - 256)];
        g_btq[idx] = __float2half_rn(v);
    } else if (idx < 262144) {
        int loc = idx - 196608;
        int n = loc / 256, k = loc % 256;
        g_btp[loc] = __float2half_rn(wp[k * 256 + n]);
    } else if (idx < 393216) {
        int loc = idx - 262144;
        int n = loc / 256, k = loc % 256;
        g_bt1[loc] = __float2half_rn(w1[k * 512 + n]);
    } else {
        int loc = idx - 393216;
        int n = loc / 512, k = loc % 512;
        g_bt2[loc] = __float2half_rn(w2[k * 256 + n]);
    }
}

// ---------------- LayerNorm -> fp16 (LN1) ----------------
template <bool PART>
__global__ void ln16_kernel(const float* __restrict__ x, const float* __restrict__ g,
                            const float* __restrict__ b, __half* __restrict__ out) {
    int warp = threadIdx.x >> 5, lane = threadIdx.x & 31;
    int t = blockIdx.x * 8 + warp;
    const float* row = x + (size_t)t * CDIM;

    float4 v0 = *(const float4*)(row + lane * 8);
    float4 v1 = *(const float4*)(row + lane * 8 + 4);

    float s = v0.x + v0.y + v0.z + v0.w + v1.x + v1.y + v1.z + v1.w;
#pragma unroll
    for (int o = 16; o; o >>= 1) s += __shfl_xor_sync(0xffffffffu, s, o);
    float mean = s * (1.f / 256.f);

    float d0x = v0.x - mean, d0y = v0.y - mean, d0z = v0.z - mean, d0w = v0.w - mean;
    float d1x = v1.x - mean, d1y = v1.y - mean, d1z = v1.z - mean, d1w = v1.w - mean;
    float vs = d0x*d0x + d0y*d0y + d0z*d0z + d0w*d0w + d1x*d1x + d1y*d1y + d1z*d1z + d1w*d1w;
#pragma unroll
    for (int o = 16; o; o >>= 1) vs += __shfl_xor_sync(0xffffffffu, vs, o);
    float rstd = rsqrtf(vs * (1.f / 256.f) + 1e-5f);

    size_t orow;
    if (PART) {
        int w = t & 63, h = (t >> 6) & 63, d = (t >> 12) & 3, bb = t >> 14;
        int win = (bb * 8 + (h >> 3)) * 8 + (w >> 3);
        int n   = d * 64 + (h & 7) * 8 + (w & 7);
        orow = (size_t)(win * 256 + n) * CDIM;
    } else {
        orow = (size_t)t * CDIM;
    }

    float4 g0 = *(const float4*)(g + lane * 8);
    float4 g1 = *(const float4*)(g + lane * 8 + 4);
    float4 b0 = *(const float4*)(b + lane * 8);
    float4 b1 = *(const float4*)(b + lane * 8 + 4);

    __half2 h0 = __floats2half2_rn(d0x * rstd * g0.x + b0.x, d0y * rstd * g0.y + b0.y);
    __half2 h1 = __floats2half2_rn(d0z * rstd * g0.z + b0.z, d0w * rstd * g0.w + b0.w);
    __half2 h2 = __floats2half2_rn(d1x * rstd * g1.x + b1.x, d1y * rstd * g1.y + b1.y);
    __half2 h3 = __floats2half2_rn(d1z * rstd * g1.z + b1.z, d1w * rstd * g1.w + b1.w);
    uint4 u;
    u.x = *(uint32_t*)&h0; u.y = *(uint32_t*)&h1; u.z = *(uint32_t*)&h2; u.w = *(uint32_t*)&h3;
    *(uint4*)&out[orow + lane * 8] = u;
}

// ---------------- HMMA GEMM (QKV): 3-stage ring, fp16 smem-staged output ----------------
template <int KDIM, int NGLOB>
__global__ __launch_bounds__(256, 2) void hmma_gemm16(
    const __half* __restrict__ A, const __half* __restrict__ BT,
    __half* __restrict__ outv)
{
    extern __shared__ __align__(128) char smring[];

    const int tid = threadIdx.x, lane = tid & 31, wid = tid >> 5;
    const int wm = wid >> 2, wn = wid & 3;
    const int tileM = blockIdx.y << 7, tileN = blockIdx.x << 7;
    const uint32_t sbase = smem_u32(smring);

    const int sr = tid >> 3, scb = tid & 7;
    const uint32_t soff0 = ((uint32_t)(sr * 128 + scb * 16));

    constexpr int NCHUNK = KDIM / 64;

    float acc[4][4][4];
#pragma unroll
    for (int mt = 0; mt < 4; mt++)
#pragma unroll
        for (int nt = 0; nt < 4; nt++)
#pragma unroll
            for (int j = 0; j < 4; j++) acc[mt][nt][j] = 0.f;

    auto stage = [&](int k0, int s) {
        uint32_t ab = sbase + s * 32768, bb = ab + 16384;
#pragma unroll
        for (int it = 0; it < 4; it++) {
            int r = sr + it * 32;
            uint32_t off = soff0 + it * 32 * 128;
            uint32_t d = ab + (off ^ ((off >> 3) & 0x70));
            CP_ASYNC16(d, A + (size_t)(tileM + r) * KDIM + k0 + scb * 8);
        }
#pragma unroll
        for (int it = 0; it < 4; it++) {
            int r = sr + it * 32;
            uint32_t off = soff0 + it * 32 * 128;
            uint32_t d = bb + (off ^ ((off >> 3) & 0x70));
            CP_ASYNC16(d, BT + (size_t)(tileN + r) * KDIM + k0 + scb * 8);
        }
    };

    stage(0, 0);
    CP_COMMIT();
    if (NCHUNK > 1) { stage(64, 1); CP_COMMIT(); }

    int sbuf = 0, snext = (NCHUNK > 1) ? 2 : 1;
#pragma unroll 1
    for (int ch = 0; ch < NCHUNK; ch++) {
        if (ch + 1 < NCHUNK) {
            asm volatile("cp.async.wait_group 1;" ::: "memory");
        } else {
            CP_WAIT0();
        }
        __syncthreads();
        if (ch + 2 < NCHUNK) {
            stage((ch + 2) * 64, snext);
            CP_COMMIT();
            snext = (snext == 2) ? 0 : snext + 1;
        }

        const uint32_t ab = sbase + sbuf * 32768, bb = ab + 16384;
#pragma unroll
        for (int ks = 0; ks < 4; ks++) {
            uint32_t bf[4][2];
#pragma unroll
            for (int bp = 0; bp < 2; bp++) {
                int nrow = wn * 32 + bp * 16 + (lane & 7) + ((lane >> 4) << 3);
                int kcol = ks * 16 + (((lane >> 3) & 1) << 3);
                uint32_t off = nrow * 128 + (kcol >> 3) * 16;
                uint32_t ad = bb + (off ^ ((off >> 3) & 0x70));
                uint32_t r0, r1, r2, r3;
                LDM_X4(r0, r1, r2, r3, ad);
                bf[bp * 2 + 0][0] = r0; bf[bp * 2 + 0][1] = r1;
                bf[bp * 2 + 1][0] = r2; bf[bp * 2 + 1][1] = r3;
            }
#pragma unroll
            for (int mt = 0; mt < 4; mt++) {
                int mrow = wm * 64 + mt * 16 + (lane & 15);
                int kcol = ks * 16 + ((lane >> 4) << 3);
                uint32_t off = mrow * 128 + (kcol >> 3) * 16;
                uint32_t ad = ab + (off ^ ((off >> 3) & 0x70));
                uint32_t a0, a1, a2, a3;
                LDM_X4(a0, a1, a2, a3, ad);
#pragma unroll
                for (int nt = 0; nt < 4; nt++)
                    MMA_161608(acc[mt][nt], a0, a1, a2, a3, bf[nt][0], bf[nt][1]);
            }
        }
        sbuf = (sbuf == 2) ? 0 : sbuf + 1;
    }

    // fp16 smem-staged coalesced stores
    __syncthreads();
    __half* tile = (__half*)smring;
    const int TS = 136;
#pragma unroll
    for (int mt = 0; mt < 4; mt++) {
#pragma unroll
        for (int rh = 0; rh < 2; rh++) {
            int rowl = wm * 64 + mt * 16 + rh * 8 + (lane >> 2);
#pragma unroll
            for (int nt = 0; nt < 4; nt++) {
                int c = wn * 32 + nt * 8 + (lane & 3) * 2;
                *(__half2*)&tile[rowl * TS + c] =
                    __floats2half2_rn(acc[mt][nt][rh * 2 + 0], acc[mt][nt][rh * 2 + 1]);
            }
        }
    }
    __syncthreads();
#pragma unroll
    for (int it = 0; it < 8; it++) {
        int linear = tid + it * 256;
        int row = linear >> 4, c16 = (linear & 15) * 8;
        uint4 v = *(uint4*)&tile[row * TS + c16];
        *(uint4*)(outv + (size_t)(tileM + row) * NGLOB + tileN + c16) = v;
    }
}

// ---------------- fused proj GEMM + residual + reverse-scatter + LayerNorm2 ----------------
__global__ __launch_bounds__(512, 1) void hmma_proj_ln(
    const __half* __restrict__ A, const __half* __restrict__ BT,
    const float* __restrict__ bias, const float* __restrict__ x,
    const float* __restrict__ lg, const float* __restrict__ lb,
    float* __restrict__ y, __half* __restrict__ xw16)
{
    extern __shared__ __align__(128) char smring[];

    const int tid = threadIdx.x, lane = tid & 31, wid = tid >> 5;
    const int wm = wid >> 3, wn = wid & 7;
    const int tileM = blockIdx.x << 7;
    const uint32_t sbase = smem_u32(smring);
    constexpr int KDIM = 256;
    constexpr int NCHUNK = 4;

    const int sr8 = tid >> 3, scb = tid & 7;

    float acc[4][4][4];
#pragma unroll
    for (int mt = 0; mt < 4; mt++)
#pragma unroll
        for (int nt = 0; nt < 4; nt++)
#pragma unroll
            for (int j = 0; j < 4; j++) acc[mt][nt][j] = 0.f;

    auto stage = [&](int k0, int s) {
        uint32_t ab = sbase + s * 49152, bb = ab + 16384;
#pragma unroll
        for (int it = 0; it < 2; it++) {
            int r = sr8 + it * 64;
            uint32_t off = (uint32_t)(r * 128 + scb * 16);
            uint32_t d = ab + (off ^ ((off >> 3) & 0x70));
            CP_ASYNC16(d, A + (size_t)(tileM + r) * KDIM + k0 + scb * 8);
        }
#pragma unroll
        for (int it = 0; it < 4; it++) {
            int r = sr8 + it * 64;
            uint32_t off = (uint32_t)(r * 128 + scb * 16);
            uint32_t d = bb + (off ^ ((off >> 3) & 0x70));
            CP_ASYNC16(d, BT + (size_t)r * KDIM + k0 + scb * 8);
        }
    };

    stage(0, 0);
    CP_COMMIT();
    stage(64, 1);
    CP_COMMIT();

    int sbuf = 0, snext = 2;
#pragma unroll 1
    for (int ch = 0; ch < NCHUNK; ch++) {
        if (ch + 1 < NCHUNK) {
            asm volatile("cp.async.wait_group 1;" ::: "memory");
        } else {
            CP_WAIT0();
        }
        __syncthreads();
        if (ch + 2 < NCHUNK) {
            stage((ch + 2) * 64, snext);
            CP_COMMIT();
            snext = (snext == 2) ? 0 : snext + 1;
        }

        const uint32_t ab = sbase + sbuf * 49152, bb = ab + 16384;
#pragma unroll
        for (int ks = 0; ks < 4; ks++) {
            uint32_t bf[4][2];
#pragma unroll
            for (int bp = 0; bp < 2; bp++) {
                int nrow = wn * 32 + bp * 16 + (lane & 7) + ((lane >> 4) << 3);
                int kcol = ks * 16 + (((lane >> 3) & 1) << 3);
                uint32_t off = nrow * 128 + (kcol >> 3) * 16;
                uint32_t ad = bb + (off ^ ((off >> 3) & 0x70));
                uint32_t r0, r1, r2, r3;
                LDM_X4(r0, r1, r2, r3, ad);
                bf[bp * 2 + 0][0] = r0; bf[bp * 2 + 0][1] = r1;
                bf[bp * 2 + 1][0] = r2; bf[bp * 2 + 1][1] = r3;
            }
#pragma unroll
            for (int mt = 0; mt < 4; mt++) {
                int mrow = wm * 64 + mt * 16 + (lane & 15);
                int kcol = ks * 16 + ((lane >> 4) << 3);
                uint32_t off = mrow * 128 + (kcol >> 3) * 16;
                uint32_t ad = ab + (off ^ ((off >> 3) & 0x70));
                uint32_t a0, a1, a2, a3;
                LDM_X4(a0, a1, a2, a3, ad);
#pragma unroll
                for (int nt = 0; nt < 4; nt++)
                    MMA_161608(acc[mt][nt], a0, a1, a2, a3, bf[nt][0], bf[nt][1]);
            }
        }
        sbuf = (sbuf == 2) ? 0 : sbuf + 1;
    }

    __syncthreads();
    float* red = (float*)smring;

    int tok[4][2];
    int rowl[4][2];
#pragma unroll
    for (int mt = 0; mt < 4; mt++) {
#pragma unroll
        for (int rh = 0; rh < 2; rh++) {
            int m = tileM + wm * 64 + mt * 16 + rh * 8 + (lane >> 2);
            int win = m >> 8, n = m & 255;
            int bb_ = win >> 6, hw = (win >> 3) & 7, ww = win & 7;
            int dz = n >> 6, hz = (n >> 3) & 7, wz = n & 7;
            tok[mt][rh] = ((bb_ * 4 + dz) * 64 + hw * 8 + hz) * 64 + ww * 8 + wz;
            rowl[mt][rh] = wm * 64 + mt * 16 + rh * 8 + (lane >> 2);

            float s = 0.f, q = 0.f;
            size_t ob = (size_t)tok[mt][rh] * 256;
#pragma unroll
            for (int nt = 0; nt < 4; nt++) {
                int c = wn * 32 + nt * 8 + (lane & 3) * 2;
                float2 rr = *(const float2*)(x + ob + c);
                float u0 = acc[mt][nt][rh * 2 + 0] + bias[c]     + rr.x;
                float u1 = acc[mt][nt][rh * 2 + 1] + bias[c + 1] + rr.y;
                acc[mt][nt][rh * 2 + 0] = u0;
                acc[mt][nt][rh * 2 + 1] = u1;
                *(float2*)(y + ob + c) = make_float2(u0, u1);
                s += u0 + u1;
                q += u0 * u0 + u1 * u1;
            }
            s += __shfl_xor_sync(0xffffffffu, s, 1);
            s += __shfl_xor_sync(0xffffffffu, s, 2);
            q += __shfl_xor_sync(0xffffffffu, q, 1);
            q += __shfl_xor_sync(0xffffffffu, q, 2);
            if ((lane & 3) == 0) {
                red[rowl[mt][rh] * 16 + wn * 2]     = s;
                red[rowl[mt][rh] * 16 + wn * 2 + 1] = q;
            }
        }
    }
    __syncthreads();

#pragma unroll
    for (int mt = 0; mt < 4; mt++) {
#pragma unroll
        for (int rh = 0; rh < 2; rh++) {
            const float* rp = red + rowl[mt][rh] * 16;
            float S = 0.f, Q = 0.f;
#pragma unroll
            for (int w = 0; w < 8; w++) { S += rp[w * 2]; Q += rp[w * 2 + 1]; }
            float mean = S * (1.f / 256.f);
            float var = Q * (1.f / 256.f) - mean * mean;
            float rstd = rsqrtf(var + 1e-5f);
            size_t ob = (size_t)tok[mt][rh] * 256;
#pragma unroll
            for (int nt = 0; nt < 4; nt++) {
                int c = wn * 32 + nt * 8 + (lane & 3) * 2;
                float h0 = (acc[mt][nt][rh * 2 + 0] - mean) * rstd * lg[c]     + lb[c];
                float h1 = (acc[mt][nt][rh * 2 + 1] - mean) * rstd * lg[c + 1] + lb[c + 1];
                *(__half2*)(xw16 + ob + c) = __floats2half2_rn(h0, h1);
            }
        }
    }
}

// ---------------- fused MLP: out = y + gelu(xw@w1 + b1) @ w2 + b2 ----------------
// One block per 128 tokens; 512 threads (16 warps, 2m x 8n).
// smem: A 4x16KB @0 | h 8x16KB @65536 | B1 ring 2x16KB @196608. Phase 2 reuses A region
// as B2 ring (2x32KB). h never touches DRAM.
__global__ __launch_bounds__(512, 1) void hmma_mlp(
    const __half* __restrict__ xw, const __half* __restrict__ BT1,
    const float* __restrict__ b1, const __half* __restrict__ BT2,
    const float* __restrict__ b2, const float* __restrict__ y,
    float* __restrict__ out)
{
    extern __shared__ __align__(128) char sm[];
    const uint32_t sbase = smem_u32(sm);
    const int tid = threadIdx.x, lane = tid & 31, wid = tid >> 5;
    const int wm = wid >> 3, wn = wid & 7;
    const int tileM = blockIdx.x << 7;
    const int sr8 = tid >> 3, scb = tid & 7;
    const uint32_t HOFF = 65536u, ROFF = 196608u;

    // ---- stage A (xw16 block, 4 chunk tiles) + first B1 tile ----
#pragma unroll
    for (int c = 0; c < 4; c++) {
#pragma unroll
        for (int it = 0; it < 2; it++) {
            int r = sr8 + it * 64;
            uint32_t off = (uint32_t)(r * 128 + scb * 16);
            uint32_t d = sbase + c * 16384 + (off ^ ((off >> 3) & 0x70));
            CP_ASYNC16(d, xw + (size_t)(tileM + r) * 256 + c * 64 + scb * 8);
        }
    }
    auto stageB1 = [&](int g, int s) {   // g = n*4+k
        int n = g >> 2, k = g & 3;
#pragma unroll
        for (int it = 0; it < 2; it++) {
            int r = sr8 + it * 64;
            uint32_t off = (uint32_t)(r * 128 + scb * 16);
            uint32_t d = sbase + ROFF + s * 16384 + (off ^ ((off >> 3) & 0x70));
            CP_ASYNC16(d, BT1 + (size_t)(n * 128 + r) * 256 + k * 64 + scb * 8);
        }
    };
    stageB1(0, 0);
    CP_COMMIT();

    // ---- phase 1: h = gelu(xw @ w1 + b1), 4 HID-chunks of 128 ----
    float acc1[4][2][4];
#pragma unroll
    for (int mt = 0; mt < 4; mt++)
#pragma unroll
        for (int nt = 0; nt < 2; nt++)
#pragma unroll
            for (int j = 0; j < 4; j++) acc1[mt][nt][j] = 0.f;

#pragma unroll 1
    for (int g = 0; g < 16; g++) {
        const int n = g >> 2, k = g & 3;
        CP_WAIT0();
        __syncthreads();
        if (g + 1 < 16) { stageB1(g + 1, (g + 1) & 1); CP_COMMIT(); }

        const uint32_t ab = sbase + k * 16384;
        const uint32_t bb = sbase + ROFF + (g & 1) * 16384;
#pragma unroll
        for (int ks = 0; ks < 4; ks++) {
            int nrow = wn * 16 + (lane & 7) + ((lane >> 4) << 3);
            int kcol = ks * 16 + (((lane >> 3) & 1) << 3);
            uint32_t off = nrow * 128 + (kcol >> 3) * 16;
            uint32_t r0, r1, r2, r3;
            LDM_X4(r0, r1, r2, r3, bb + (off ^ ((off >> 3) & 0x70)));
#pragma unroll
            for (int mt = 0; mt < 4; mt++) {
                int mrow = wm * 64 + mt * 16 + (lane & 15);
                int kc2 = ks * 16 + ((lane >> 4) << 3);
                uint32_t offa = mrow * 128 + (kc2 >> 3) * 16;
                uint32_t a0, a1, a2, a3;
                LDM_X4(a0, a1, a2, a3, ab + (offa ^ ((offa >> 3) & 0x70)));
                MMA_161608(acc1[mt][0], a0, a1, a2, a3, r0, r1);
                MMA_161608(acc1[mt][1], a0, a1, a2, a3, r2, r3);
            }
        }

        if (k == 3) {
            // epilogue for HID chunk n: gelu(+b1) -> h smem tiles
#pragma unroll
            for (int mt = 0; mt < 4; mt++) {
#pragma unroll
                for (int rh = 0; rh < 2; rh++) {
                    int rowl = wm * 64 + mt * 16 + rh * 8 + (lane >> 2);
#pragma unroll
                    for (int nt = 0; nt < 2; nt++) {
                        int hc = n * 128 + wn * 16 + nt * 8 + (lane & 3) * 2;
                        float v0 = gelu_exact(acc1[mt][nt][rh * 2 + 0] + b1[hc]);
                        float v1 = gelu_exact(acc1[mt][nt][rh * 2 + 1] + b1[hc + 1]);
                        int t = hc >> 6, cc = hc & 63;
                        uint32_t boff = (uint32_t)(rowl * 128 + cc * 2);
                        uint32_t d = sbase + HOFF + t * 16384 + (boff ^ ((boff >> 3) & 0x70));
                        __half2 hv = __floats2half2_rn(v0, v1);
                        asm volatile("st.shared.b32 [%0], %1;" :: "r"(d), "r"(*(uint32_t*)&hv));
                        acc1[mt][nt][rh * 2 + 0] = 0.f;
                        acc1[mt][nt][rh * 2 + 1] = 0.f;
                    }
                }
            }
        }
    }
    __syncthreads();   // h complete; A region free

    // ---- phase 2: out = h @ w2 + b2 + y ----
    auto stageB2 = [&](int k, int s) {
#pragma unroll
        for (int it = 0; it < 4; it++) {
            int r = sr8 + it * 64;
            uint32_t off = (uint32_t)(r * 128 + scb * 16);
            uint32_t d = sbase + s * 32768 + (off ^ ((off >> 3) & 0x70));
            CP_ASYNC16(d, BT2 + (size_t)r * 512 + k * 64 + scb * 8);
        }
    };
    stageB2(0, 0);
    CP_COMMIT();

    float acc2[4][4][4];
#pragma unroll
    for (int mt = 0; mt < 4; mt++)
#pragma unroll
        for (int nt = 0; nt < 4; nt++)
#pragma unroll
            for (int j = 0; j < 4; j++) acc2[mt][nt][j] = 0.f;

#pragma unroll 1
    for (int k = 0; k < 8; k++) {
        CP_WAIT0();
        __syncthreads();
        if (k + 1 < 8) { stageB2(k + 1, (k + 1) & 1); CP_COMMIT(); }

        const uint32_t ab = sbase + HOFF + k * 16384;
        const uint32_t bb = sbase + (k & 1) * 32768;
#pragma unroll
        for (int ks = 0; ks < 4; ks++) {
            uint32_t bf[4][2];
#pragma unroll
            for (int bp = 0; bp < 2; bp++) {
                int nrow = wn * 32 + bp * 16 + (lane & 7) + ((lane >> 4) << 3);
                int kcol = ks * 16 + (((lane >> 3) & 1) << 3);
                uint32_t off = nrow * 128 + (kcol >> 3) * 16;
                uint32_t r0, r1, r2, r3;
                LDM_X4(r0, r1, r2, r3, bb + (off ^ ((off >> 3) & 0x70)));
                bf[bp * 2 + 0][0] = r0; bf[bp * 2 + 0][1] = r1;
                bf[bp * 2 + 1][0] = r2; bf[bp * 2 + 1][1] = r3;
            }
#pragma unroll
            for (int mt = 0; mt < 4; mt++) {
                int mrow = wm * 64 + mt * 16 + (lane & 15);
                int kc2 = ks * 16 + ((lane >> 4) << 3);
                uint32_t offa = mrow * 128 + (kc2 >> 3) * 16;
                uint32_t a0, a1, a2, a3;
                LDM_X4(a0, a1, a2, a3, ab + (offa ^ ((offa >> 3) & 0x70)));
#pragma unroll
                for (int nt = 0; nt < 4; nt++)
                    MMA_161608(acc2[mt][nt], a0, a1, a2, a3, bf[nt][0], bf[nt][1]);
            }
        }
    }

    // epilogue: out = acc2 + b2 + y (fp32, 8B contiguous per thread-pair)
#pragma unroll
    for (int mt = 0; mt < 4; mt++) {
#pragma unroll
        for (int rh = 0; rh < 2; rh++) {
            int m = tileM + wm * 64 + mt * 16 + rh * 8 + (lane >> 2);
            size_t ob = (size_t)m * 256;
#pragma unroll
            for (int nt = 0; nt < 4; nt++) {
                int c = wn * 32 + nt * 8 + (lane & 3) * 2;
                const float* rr = y + ob + c;
                *(float2*)(out + ob + c) =
                    make_float2(acc2[mt][nt][rh * 2 + 0] + b2[c] + rr[0],
                                acc2[mt][nt][rh * 2 + 1] + b2[c + 1] + rr[1]);
            }
        }
    }
}

// ---------------- windowed attention: one block per (head, window), slice loop ----------------
__global__ __launch_bounds__(256, 2) void attn_mma_kernel(
    const __half* __restrict__ qkv, const float* __restrict__ rpb,
    __half* __restrict__ out)
{
    extern __shared__ char smraw[];
    __half* Qs = (__half*)smraw;            // [256][40]
    __half* Ks = Qs + 256 * 40;             // [256][40]
    __half* Vs = Ks + 256 * 40;             // [256][40]
    float*  Bt  = (float*)(Vs + 256 * 40);  // [7][225], reversed in dw
    float*  Om1 = Bt + 1575;                // [2][4][16][32]
    float*  Ms1 = Om1 + 4096;               // [2][4][16]
    float*  Ss1 = Ms1 + 128;                // [2][4][16]

    const int hh = blockIdx.x, win = blockIdx.y;
    const int tid = threadIdx.x, lane = tid & 31, warp = tid >> 5;
    const int qg = warp & 3, kh = warp >> 2;
    const size_t base = (size_t)win * 256 * QKVDIM;

    if (tid < 225) {
        int dh30 = (tid / 15) * 30;
#pragma unroll
        for (int off = 0; off < 7; off++)
            Bt[off * 225 + tid] = rpb[(off * 225 + dh30 + 14 - tid) * 8 + hh];
    }
#pragma unroll
    for (int r = 0; r < 4; r++) {
        int idx = tid + r * 256;
        int q = idx >> 2, c8 = idx & 3;
        const __half* src = qkv + base + (size_t)q * QKVDIM + hh * 32 + c8 * 8;
        *(uint4*)(Qs + q * 40 + c8 * 8) = *(const uint4*)src;
        *(uint4*)(Ks + q * 40 + c8 * 8) = *(const uint4*)(src + 256);
        *(uint4*)(Vs + q * 40 + c8 * 8) = *(const uint4*)(src + 512);
    }
    __syncthreads();

    const int qrow_l = qg * 16 + (lane >> 2);
    const int hq0 = qrow_l >> 3, wq = qrow_l & 7;
    const int hq1 = (qrow_l + 8) >> 3;
    const int j0 = 2 * (lane & 3) - wq + 7;
    const int base0 = (hq0 + 7) * 15 + j0;
    const int base1 = (hq1 + 7) * 15 + j0;
    const int r0l = lane >> 2;
    const int c2 = 2 * (lane & 3);

#pragma unroll 1
    for (int i = 0; i < 4; i++) {
        const int p = i & 1;
        uint32_t qf[2][4];
#pragma unroll
        for (int ks = 0; ks < 2; ks++) {
            uint32_t ad = smem_u32(Qs + (i * 64 + qg * 16 + (lane & 15)) * 40
                                      + ((lane >> 4) + ks * 2) * 8);
            LDM_X4(qf[ks][0], qf[ks][1], qf[ks][2], qf[ks][3], ad);
        }

        float sacc[12][4];
#pragma unroll
        for (int nb = 0; nb < 12; nb++) {
            sacc[nb][0] = 0.f; sacc[nb][1] = 0.f; sacc[nb][2] = 0.f; sacc[nb][3] = 0.f;
        }
#pragma unroll
        for (int kg = 0; kg < 6; kg++) {
            int c = kh * 96 + kg * 16;
            int gb = (c >= i * 64) ? c + 64 : c;
#pragma unroll
            for (int ks = 0; ks < 2; ks++) {
                uint32_t ad = smem_u32(Ks + (gb + (lane & 7) + ((lane >> 4) << 3)) * 40
                                          + (((lane >> 3) & 1) + ks * 2) * 8);
                uint32_t r0, r1, r2, r3;
                LDM_X4(r0, r1, r2, r3, ad);
                MMA_161608(sacc[kg * 2 + 0], qf[ks][0], qf[ks][1], qf[ks][2], qf[ks][3], r0, r1);
                MMA_161608(sacc[kg * 2 + 1], qf[ks][0], qf[ks][1], qf[ks][2], qf[ks][3], r2, r3);
            }
        }

        float mx0 = -1e30f, mx1 = -1e30f;
#pragma unroll
        for (int nb = 0; nb < 12; nb++) {
            int t12 = kh * 12 + nb;
            int hk15 = (t12 & 7) * 15;
            int kb = t12 * 8;
            int dk = (t12 >> 3) + ((kb >= i * 64) ? 1 : 0);
            const float* bt = Bt + (i - dk + 3) * 225;
            sacc[nb][0] += bt[base0 - hk15];
            sacc[nb][1] += bt[base0 - hk15 + 1];
            sacc[nb][2] += bt[base1 - hk15];
            sacc[nb][3] += bt[base1 - hk15 + 1];
            mx0 = fmaxf(mx0, fmaxf(sacc[nb][0], sacc[nb][1]));
            mx1 = fmaxf(mx1, fmaxf(sacc[nb][2], sacc[nb][3]));
        }
        mx0 = fmaxf(mx0, __shfl_xor_sync(0xffffffffu, mx0, 1));
        mx0 = fmaxf(mx0, __shfl_xor_sync(0xffffffffu, mx0, 2));
        mx1 = fmaxf(mx1, __shfl_xor_sync(0xffffffffu, mx1, 1));
        mx1 = fmaxf(mx1, __shfl_xor_sync(0xffffffffu, mx1, 2));

        float s0 = 0.f, s1 = 0.f;
        uint32_t pf[12][2];
#pragma unroll
        for (int nb = 0; nb < 12; nb++) {
            float e0 = __expf(sacc[nb][0] - mx0);
            float e1 = __expf(sacc[nb][1] - mx0);
            float e2 = __expf(sacc[nb][2] - mx1);
            float e3 = __expf(sacc[nb][3] - mx1);
            s0 += e0 + e1; s1 += e2 + e3;
            __half2 p01 = __floats2half2_rn(e0, e1);
            __half2 p23 = __floats2half2_rn(e2, e3);
            pf[nb][0] = *(uint32_t*)&p01;
            pf[nb][1] = *(uint32_t*)&p23;
        }
        s0 += __shfl_xor_sync(0xffffffffu, s0, 1);
        s0 += __shfl_xor_sync(0xffffffffu, s0, 2);
        s1 += __shfl_xor_sync(0xffffffffu, s1, 1);
        s1 += __shfl_xor_sync(0xffffffffu, s1, 2);

        float oacc[4][4];
#pragma unroll
        for (int nb = 0; nb < 4; nb++) {
            oacc[nb][0] = 0.f; oacc[nb][1] = 0.f; oacc[nb][2] = 0.f; oacc[nb][3] = 0.f;
        }
#pragma unroll
        for (int kt = 0; kt < 6; kt++) {
            int c = kh * 96 + kt * 16;
            int gb = (c >= i * 64) ? c + 64 : c;
            uint32_t a0 = pf[kt * 2][0],     a1 = pf[kt * 2][1];
            uint32_t a2 = pf[kt * 2 + 1][0], a3 = pf[kt * 2 + 1][1];
#pragma unroll
            for (int dh2 = 0; dh2 < 2; dh2++) {
                uint32_t ad = smem_u32(Vs + (gb + (lane & 7) + (((lane >> 3) & 1) << 3)) * 40
                                          + dh2 * 16 + ((lane >> 4) << 3));
                uint32_t v0, v1, v2, v3;
                asm volatile("ldmatrix.sync.aligned.m8n8.x4.trans.shared.b16 {%0,%1,%2,%3}, [%4];"
                             : "=r"(v0), "=r"(v1), "=r"(v2), "=r"(v3) : "r"(ad));
                MMA_161608(oacc[dh2 * 2 + 0], a0, a1, a2, a3, v0, v1);
                MMA_161608(oacc[dh2 * 2 + 1], a0, a1, a2, a3, v2, v3);
            }
        }

        float* Om = Om1 + p * 2048;
        float* Ms = Ms1 + p * 64;
        float* Ss = Ss1 + p * 64;
        if (kh == 1) {
            if ((lane & 3) == 0) {
                Ms[qg * 16 + r0l]     = mx0;  Ss[qg * 16 + r0l]     = s0;
                Ms[qg * 16 + 8 + r0l] = mx1;  Ss[qg * 16 + 8 + r0l] = s1;
            }
            float* om = Om + qg * 512;
#pragma unroll
            for (int nb = 0; nb < 4; nb++) {
                om[r0l * 32 + nb * 8 + c2]           = oacc[nb][0];
                om[r0l * 32 + nb * 8 + c2 + 1]       = oacc[nb][1];
                om[(8 + r0l) * 32 + nb * 8 + c2]     = oacc[nb][2];
                om[(8 + r0l) * 32 + nb * 8 + c2 + 1] = oacc[nb][3];
            }
        }
        __syncthreads();
        if (kh == 0) {
            float mB0 = Ms[qg * 16 + r0l],     sB0 = Ss[qg * 16 + r0l];
            float mB1 = Ms[qg * 16 + 8 + r0l], sB1 = Ss[qg * 16 + 8 + r0l];
            float m0 = fmaxf(mx0, mB0), m1 = fmaxf(mx1, mB1);
            float a0 = __expf(mx0 - m0), b0 = __expf(mB0 - m0);
            float a1 = __expf(mx1 - m1), b1 = __expf(mB1 - m1);
            float inv0 = 1.f / (a0 * s0 + b0 * sB0);
            float inv1 = 1.f / (a1 * s1 + b1 * sB1);
            const float* om = Om + qg * 512;
            size_t o0 = ((size_t)(win * 256 + i * 64 + qrow_l)) * 256 + hh * 32;
#pragma unroll
            for (int nb = 0; nb < 4; nb++) {
                int c = nb * 8 + c2;
                float v0 = (a0 * oacc[nb][0] + b0 * om[r0l * 32 + c])           * inv0;
                float v1 = (a0 * oacc[nb][1] + b0 * om[r0l * 32 + c + 1])       * inv0;
                float v2 = (a1 * oacc[nb][2] + b1 * om[(8 + r0l) * 32 + c])     * inv1;
                float v3 = (a1 * oacc[nb][3] + b1 * om[(8 + r0l) * 32 + c + 1]) * inv1;
                *(__half2*)(out + o0 + c)           = __floats2half2_rn(v0, v1);
                *(__half2*)(out + o0 + 8 * 256 + c) = __floats2half2_rn(v2, v3);
            }
        }
    }
}

// ---------------- launch ----------------
extern "C" void kernel_launch(void* const* d_in, const int* in_sizes, int n_in,
                              void* d_out, int out_size) {
    const float* x     = (const float*)d_in[0];
    const float* ln1_g = (const float*)d_in[1];
    const float* ln1_b = (const float*)d_in[2];
    const float* ln2_g = (const float*)d_in[3];
    const float* ln2_b = (const float*)d_in[4];
    const float* wq    = (const float*)d_in[5];
    const float* wkv   = (const float*)d_in[6];
    const float* wp    = (const float*)d_in[7];
    const float* bp    = (const float*)d_in[8];
    const float* rpb   = (const float*)d_in[9];
    const float* w1    = (const float*)d_in[10];
    const float* b1    = (const float*)d_in[11];
    const float* w2    = (const float*)d_in[12];
    const float* b2    = (const float*)d_in[13];
    float* out = (float*)d_out;

    float *y;
    __half *qkv16, *xw16, *attn16, *btq, *btp, *bt1, *bt2;
    cudaGetSymbolAddress((void**)&qkv16,  g_qkv16);
    cudaGetSymbolAddress((void**)&y,      g_y);
    cudaGetSymbolAddress((void**)&xw16,   g_xw16);
    cudaGetSymbolAddress((void**)&attn16, g_attn16);
    cudaGetSymbolAddress((void**)&btq,    g_btq);
    cudaGetSymbolAddress((void**)&btp,    g_btp);
    cudaGetSymbolAddress((void**)&bt1,    g_bt1);
    cudaGetSymbolAddress((void**)&bt2,    g_bt2);

    const int ATTN_SMEM = 61440 + 23708;  // 85148
    cudaFuncSetAttribute(attn_mma_kernel, cudaFuncAttributeMaxDynamicSharedMemorySize, ATTN_SMEM);

    const int GEMM_SMEM = 3 * 32768;      // 98304
    cudaFuncSetAttribute(hmma_gemm16<256,768>, cudaFuncAttributeMaxDynamicSharedMemorySize, GEMM_SMEM);

    const int PROJ_SMEM = 3 * 49152;      // 147456
    cudaFuncSetAttribute(hmma_proj_ln, cudaFuncAttributeMaxDynamicSharedMemorySize, PROJ_SMEM);

    const int MLP_SMEM = 229376;          // A 64K + h 128K + B1 ring 32K
    cudaFuncSetAttribute(hmma_mlp, cudaFuncAttributeMaxDynamicSharedMemorySize, MLP_SMEM);

    prep_w_kernel<<<2048, 256>>>(wq, wkv, wp, w1, w2);
    ln16_kernel<true><<<TOKENS / 8, 256>>>(x, ln1_g, ln1_b, xw16);
    hmma_gemm16<256,768><<<dim3(6, TOKENS / 128), 256, GEMM_SMEM>>>(xw16, btq, qkv16);
    attn_mma_kernel<<<dim3(8, 512), 256, ATTN_SMEM>>>(qkv16, rpb, attn16);
    hmma_proj_ln<<<TOKENS / 128, 512, PROJ_SMEM>>>(attn16, btp, bp, x, ln2_g, ln2_b, y, xw16);
    hmma_mlp<<<TOKENS / 128, 512, MLP_SMEM>>>(xw16, bt1, b1, bt2, b2, y, out);
}

// round 16
// speedup vs baseline: 1.0770x; 1.0770x over previous
#include <cuda_runtime.h>
#include <cuda_fp16.h>
#include <math.h>
#include <stdint.h>

#define TOKENS   131072
#define CDIM     256
#define QKVDIM   768
#define HIDDIM   512

// ---------------- scratch ----------------
__device__ __half g_qkv16[100663296];  // (131072, 768) fp16
__device__ __half g_y16  [33554432];   // (131072, 256) fp16 residual stream
__device__ __half g_xw16 [33554432];   // (131072, 256) fp16
__device__ __half g_attn16[33554432];  // (131072, 256) fp16 (window layout)
__device__ __half g_h16  [67108864];   // (131072, 512) fp16
__device__ __half g_btq  [196608];     // [768,256]  = [wq*scale | wkv]^T
__device__ __half g_btp  [65536];      // [256,256]  = wp^T
__device__ __half g_bt1  [131072];     // [512,256]  = w1^T
__device__ __half g_bt2  [131072];     // [256,512]  = w2^T

// ---------------- helpers ----------------
__device__ __forceinline__ uint32_t smem_u32(const void* p) {
    uint32_t a;
    asm("{ .reg .u64 t; cvta.to.shared.u64 t, %1; cvt.u32.u64 %0, t; }" : "=r"(a) : "l"(p));
    return a;
}
__device__ __forceinline__ float gelu_exact(float x) {
    return 0.5f * x * (1.0f + erff(x * 0.70710678118654752f));
}
#define MMA_161608(ACC, A0,A1,A2,A3, B0,B1) \
    asm volatile( \
        "mma.sync.aligned.m16n8k16.row.col.f32.f16.f16.f32 " \
        "{%0,%1,%2,%3}, {%4,%5,%6,%7}, {%8,%9}, {%0,%1,%2,%3};" \
        : "+f"((ACC)[0]), "+f"((ACC)[1]), "+f"((ACC)[2]), "+f"((ACC)[3]) \
        : "r"(A0), "r"(A1), "r"(A2), "r"(A3), "r"(B0), "r"(B1))
#define CP_ASYNC16(dst, src) \
    asm volatile("cp.async.cg.shared.global [%0], [%1], 16;" :: "r"(dst), "l"(src))
#define CP_COMMIT() asm volatile("cp.async.commit_group;")
#define CP_WAIT0()  asm volatile("cp.async.wait_group 0;" ::: "memory")
#define LDM_X4(R0,R1,R2,R3,AD) \
    asm volatile("ldmatrix.sync.aligned.m8n8.x4.shared.b16 {%0,%1,%2,%3}, [%4];" \
                 : "=r"(R0), "=r"(R1), "=r"(R2), "=r"(R3) : "r"(AD))

// ---------------- weight prep ----------------
__global__ void prep_w_kernel(const float* __restrict__ wq, const float* __restrict__ wkv,
                              const float* __restrict__ wp, const float* __restrict__ w1,
                              const float* __restrict__ w2) {
    const float scale = 0.17677669529663687f;
    int idx = blockIdx.x * 256 + threadIdx.x;   // 524288 total
    if (idx < 196608) {
        int n = idx / 256, k = idx % 256;
        float v = (n < 256) ? wq[k * 256 + n] * scale : wkv[k * 512 + (n - 256)];
        g_btq[idx] = __float2half_rn(v);
    } else if (idx < 262144) {
        int loc = idx - 196608;
        int n = loc / 256, k = loc % 256;
        g_btp[loc] = __float2half_rn(wp[k * 256 + n]);
    } else if (idx < 393216) {
        int loc = idx - 262144;
        int n = loc / 256, k = loc % 256;
        g_bt1[loc] = __float2half_rn(w1[k * 512 + n]);
    } else {
        int loc = idx - 393216;
        int n = loc / 512, k = loc % 512;
        g_bt2[loc] = __float2half_rn(w2[k * 256 + n]);
    }
}

// ---------------- LayerNorm -> fp16 (LN1) ----------------
template <bool PART>
__global__ void ln16_kernel(const float* __restrict__ x, const float* __restrict__ g,
                            const float* __restrict__ b, __half* __restrict__ out) {
    int warp = threadIdx.x >> 5, lane = threadIdx.x & 31;
    int t = blockIdx.x * 8 + warp;
    const float* row = x + (size_t)t * CDIM;

    float4 v0 = *(const float4*)(row + lane * 8);
    float4 v1 = *(const float4*)(row + lane * 8 + 4);

    float s = v0.x + v0.y + v0.z + v0.w + v1.x + v1.y + v1.z + v1.w;
#pragma unroll
    for (int o = 16; o; o >>= 1) s += __shfl_xor_sync(0xffffffffu, s, o);
    float mean = s * (1.f / 256.f);

    float d0x = v0.x - mean, d0y = v0.y - mean, d0z = v0.z - mean, d0w = v0.w - mean;
    float d1x = v1.x - mean, d1y = v1.y - mean, d1z = v1.z - mean, d1w = v1.w - mean;
    float vs = d0x*d0x + d0y*d0y + d0z*d0z + d0w*d0w + d1x*d1x + d1y*d1y + d1z*d1z + d1w*d1w;
#pragma unroll
    for (int o = 16; o; o >>= 1) vs += __shfl_xor_sync(0xffffffffu, vs, o);
    float rstd = rsqrtf(vs * (1.f / 256.f) + 1e-5f);

    size_t orow;
    if (PART) {
        int w = t & 63, h = (t >> 6) & 63, d = (t >> 12) & 3, bb = t >> 14;
        int win = (bb * 8 + (h >> 3)) * 8 + (w >> 3);
        int n   = d * 64 + (h & 7) * 8 + (w & 7);
        orow = (size_t)(win * 256 + n) * CDIM;
    } else {
        orow = (size_t)t * CDIM;
    }

    float4 g0 = *(const float4*)(g + lane * 8);
    float4 g1 = *(const float4*)(g + lane * 8 + 4);
    float4 b0 = *(const float4*)(b + lane * 8);
    float4 b1 = *(const float4*)(b + lane * 8 + 4);

    __half2 h0 = __floats2half2_rn(d0x * rstd * g0.x + b0.x, d0y * rstd * g0.y + b0.y);
    __half2 h1 = __floats2half2_rn(d0z * rstd * g0.z + b0.z, d0w * rstd * g0.w + b0.w);
    __half2 h2 = __floats2half2_rn(d1x * rstd * g1.x + b1.x, d1y * rstd * g1.y + b1.y);
    __half2 h3 = __floats2half2_rn(d1z * rstd * g1.z + b1.z, d1w * rstd * g1.w + b1.w);
    uint4 u;
    u.x = *(uint32_t*)&h0; u.y = *(uint32_t*)&h1; u.z = *(uint32_t*)&h2; u.w = *(uint32_t*)&h3;
    *(uint4*)&out[orow + lane * 8] = u;
}

// ---------------- HMMA GEMM with 3-stage cp.async ring ----------------
// MODE 1: gelu(+bias)->fp16 (smem-staged coalesced stores).
// MODE 3: +bias + fp16 res -> fp32. MODE 4: fp16 out, no bias (smem-staged).
template <int MODE, int KDIM, int NGLOB>
__global__ __launch_bounds__(256, 2) void hmma_gemm(
    const __half* __restrict__ A, const __half* __restrict__ BT,
    const float* __restrict__ bias, const void* __restrict__ resv,
    void* __restrict__ outv)
{
    extern __shared__ __align__(128) char smring[];

    const int tid = threadIdx.x, lane = tid & 31, wid = tid >> 5;
    const int wm = wid >> 2, wn = wid & 3;
    const int tileM = blockIdx.y << 7, tileN = blockIdx.x << 7;
    const uint32_t sbase = smem_u32(smring);

    const int sr = tid >> 3, scb = tid & 7;
    const uint32_t soff0 = ((uint32_t)(sr * 128 + scb * 16));

    constexpr int NCHUNK = KDIM / 64;

    float acc[4][4][4];
#pragma unroll
    for (int mt = 0; mt < 4; mt++)
#pragma unroll
        for (int nt = 0; nt < 4; nt++)
#pragma unroll
            for (int j = 0; j < 4; j++) acc[mt][nt][j] = 0.f;

    auto stage = [&](int k0, int s) {
        uint32_t ab = sbase + s * 32768, bb = ab + 16384;
#pragma unroll
        for (int it = 0; it < 4; it++) {
            int r = sr + it * 32;
            uint32_t off = soff0 + it * 32 * 128;
            uint32_t d = ab + (off ^ ((off >> 3) & 0x70));
            CP_ASYNC16(d, A + (size_t)(tileM + r) * KDIM + k0 + scb * 8);
        }
#pragma unroll
        for (int it = 0; it < 4; it++) {
            int r = sr + it * 32;
            uint32_t off = soff0 + it * 32 * 128;
            uint32_t d = bb + (off ^ ((off >> 3) & 0x70));
            CP_ASYNC16(d, BT + (size_t)(tileN + r) * KDIM + k0 + scb * 8);
        }
    };

    stage(0, 0);
    CP_COMMIT();
    if (NCHUNK > 1) { stage(64, 1); CP_COMMIT(); }

    int sbuf = 0, snext = (NCHUNK > 1) ? 2 : 1;
#pragma unroll 1
    for (int ch = 0; ch < NCHUNK; ch++) {
        if (ch + 1 < NCHUNK) {
            asm volatile("cp.async.wait_group 1;" ::: "memory");
        } else {
            CP_WAIT0();
        }
        __syncthreads();
        if (ch + 2 < NCHUNK) {
            stage((ch + 2) * 64, snext);
            CP_COMMIT();
            snext = (snext == 2) ? 0 : snext + 1;
        }

        const uint32_t ab = sbase + sbuf * 32768, bb = ab + 16384;
#pragma unroll
        for (int ks = 0; ks < 4; ks++) {
            uint32_t bf[4][2];
#pragma unroll
            for (int bp = 0; bp < 2; bp++) {
                int nrow = wn * 32 + bp * 16 + (lane & 7) + ((lane >> 4) << 3);
                int kcol = ks * 16 + (((lane >> 3) & 1) << 3);
                uint32_t off = nrow * 128 + (kcol >> 3) * 16;
                uint32_t ad = bb + (off ^ ((off >> 3) & 0x70));
                uint32_t r0, r1, r2, r3;
                LDM_X4(r0, r1, r2, r3, ad);
                bf[bp * 2 + 0][0] = r0; bf[bp * 2 + 0][1] = r1;
                bf[bp * 2 + 1][0] = r2; bf[bp * 2 + 1][1] = r3;
            }
#pragma unroll
            for (int mt = 0; mt < 4; mt++) {
                int mrow = wm * 64 + mt * 16 + (lane & 15);
                int kcol = ks * 16 + ((lane >> 4) << 3);
                uint32_t off = mrow * 128 + (kcol >> 3) * 16;
                uint32_t ad = ab + (off ^ ((off >> 3) & 0x70));
                uint32_t a0, a1, a2, a3;
                LDM_X4(a0, a1, a2, a3, ad);
#pragma unroll
                for (int nt = 0; nt < 4; nt++)
                    MMA_161608(acc[mt][nt], a0, a1, a2, a3, bf[nt][0], bf[nt][1]);
            }
        }
        sbuf = (sbuf == 2) ? 0 : sbuf + 1;
    }

    if (MODE == 3) {
#pragma unroll
        for (int mt = 0; mt < 4; mt++) {
#pragma unroll
            for (int rh = 0; rh < 2; rh++) {
                int m = tileM + wm * 64 + mt * 16 + rh * 8 + (lane >> 2);
                size_t obase = (size_t)m * NGLOB;
#pragma unroll
                for (int nt = 0; nt < 4; nt++) {
                    int c = tileN + wn * 32 + nt * 8 + (lane & 3) * 2;
                    __half2 rr16 = *(const __half2*)((const __half*)resv + obase + c);
                    float2 rr = __half22float2(rr16);
                    *(float2*)((float*)outv + obase + c) =
                        make_float2(acc[mt][nt][rh * 2 + 0] + bias[c] + rr.x,
                                    acc[mt][nt][rh * 2 + 1] + bias[c + 1] + rr.y);
                }
            }
        }
    } else {
        // fp16 path: stage through smem, emit coalesced 16B stores
        __syncthreads();
        __half* tile = (__half*)smring;
        const int TS = 136;
#pragma unroll
        for (int mt = 0; mt < 4; mt++) {
#pragma unroll
            for (int rh = 0; rh < 2; rh++) {
                int rowl = wm * 64 + mt * 16 + rh * 8 + (lane >> 2);
#pragma unroll
                for (int nt = 0; nt < 4; nt++) {
                    int c = wn * 32 + nt * 8 + (lane & 3) * 2;
                    float v0 = acc[mt][nt][rh * 2 + 0];
                    float v1 = acc[mt][nt][rh * 2 + 1];
                    if (MODE == 1) {
                        v0 = gelu_exact(v0 + bias[tileN + c]);
                        v1 = gelu_exact(v1 + bias[tileN + c + 1]);
                    }
                    *(__half2*)&tile[rowl * TS + c] = __floats2half2_rn(v0, v1);
                }
            }
        }
        __syncthreads();
#pragma unroll
        for (int it = 0; it < 8; it++) {
            int linear = tid + it * 256;
            int row = linear >> 4, c16 = (linear & 15) * 8;
            uint4 v = *(uint4*)&tile[row * TS + c16];
            *(uint4*)((__half*)outv + (size_t)(tileM + row) * NGLOB + tileN + c16) = v;
        }
    }
}

// ---------------- fused proj GEMM + residual + reverse-scatter + LayerNorm2 ----------------
// y is emitted fp16 (residual stream); LN2 uses fp32 registers before rounding.
__global__ __launch_bounds__(512, 1) void hmma_proj_ln(
    const __half* __restrict__ A, const __half* __restrict__ BT,
    const float* __restrict__ bias, const float* __restrict__ x,
    const float* __restrict__ lg, const float* __restrict__ lb,
    __half* __restrict__ y, __half* __restrict__ xw16)
{
    extern __shared__ __align__(128) char smring[];

    const int tid = threadIdx.x, lane = tid & 31, wid = tid >> 5;
    const int wm = wid >> 3, wn = wid & 7;
    const int tileM = blockIdx.x << 7;
    const uint32_t sbase = smem_u32(smring);
    constexpr int KDIM = 256;
    constexpr int NCHUNK = 4;

    const int sr8 = tid >> 3, scb = tid & 7;

    float acc[4][4][4];
#pragma unroll
    for (int mt = 0; mt < 4; mt++)
#pragma unroll
        for (int nt = 0; nt < 4; nt++)
#pragma unroll
            for (int j = 0; j < 4; j++) acc[mt][nt][j] = 0.f;

    auto stage = [&](int k0, int s) {
        uint32_t ab = sbase + s * 49152, bb = ab + 16384;
#pragma unroll
        for (int it = 0; it < 2; it++) {
            int r = sr8 + it * 64;
            uint32_t off = (uint32_t)(r * 128 + scb * 16);
            uint32_t d = ab + (off ^ ((off >> 3) & 0x70));
            CP_ASYNC16(d, A + (size_t)(tileM + r) * KDIM + k0 + scb * 8);
        }
#pragma unroll
        for (int it = 0; it < 4; it++) {
            int r = sr8 + it * 64;
            uint32_t off = (uint32_t)(r * 128 + scb * 16);
            uint32_t d = bb + (off ^ ((off >> 3) & 0x70));
            CP_ASYNC16(d, BT + (size_t)r * KDIM + k0 + scb * 8);
        }
    };

    stage(0, 0);
    CP_COMMIT();
    stage(64, 1);
    CP_COMMIT();

    int sbuf = 0, snext = 2;
#pragma unroll 1
    for (int ch = 0; ch < NCHUNK; ch++) {
        if (ch + 1 < NCHUNK) {
            asm volatile("cp.async.wait_group 1;" ::: "memory");
        } else {
            CP_WAIT0();
        }
        __syncthreads();
        if (ch + 2 < NCHUNK) {
            stage((ch + 2) * 64, snext);
            CP_COMMIT();
            snext = (snext == 2) ? 0 : snext + 1;
        }

        const uint32_t ab = sbase + sbuf * 49152, bb = ab + 16384;
#pragma unroll
        for (int ks = 0; ks < 4; ks++) {
            uint32_t bf[4][2];
#pragma unroll
            for (int bp = 0; bp < 2; bp++) {
                int nrow = wn * 32 + bp * 16 + (lane & 7) + ((lane >> 4) << 3);
                int kcol = ks * 16 + (((lane >> 3) & 1) << 3);
                uint32_t off = nrow * 128 + (kcol >> 3) * 16;
                uint32_t ad = bb + (off ^ ((off >> 3) & 0x70));
                uint32_t r0, r1, r2, r3;
                LDM_X4(r0, r1, r2, r3, ad);
                bf[bp * 2 + 0][0] = r0; bf[bp * 2 + 0][1] = r1;
                bf[bp * 2 + 1][0] = r2; bf[bp * 2 + 1][1] = r3;
            }
#pragma unroll
            for (int mt = 0; mt < 4; mt++) {
                int mrow = wm * 64 + mt * 16 + (lane & 15);
                int kcol = ks * 16 + ((lane >> 4) << 3);
                uint32_t off = mrow * 128 + (kcol >> 3) * 16;
                uint32_t ad = ab + (off ^ ((off >> 3) & 0x70));
                uint32_t a0, a1, a2, a3;
                LDM_X4(a0, a1, a2, a3, ad);
#pragma unroll
                for (int nt = 0; nt < 4; nt++)
                    MMA_161608(acc[mt][nt], a0, a1, a2, a3, bf[nt][0], bf[nt][1]);
            }
        }
        sbuf = (sbuf == 2) ? 0 : sbuf + 1;
    }

    __syncthreads();
    float* red = (float*)smring;

    int tok[4][2];
    int rowl[4][2];
#pragma unroll
    for (int mt = 0; mt < 4; mt++) {
#pragma unroll
        for (int rh = 0; rh < 2; rh++) {
            int m = tileM + wm * 64 + mt * 16 + rh * 8 + (lane >> 2);
            int win = m >> 8, n = m & 255;
            int bb_ = win >> 6, hw = (win >> 3) & 7, ww = win & 7;
            int dz = n >> 6, hz = (n >> 3) & 7, wz = n & 7;
            tok[mt][rh] = ((bb_ * 4 + dz) * 64 + hw * 8 + hz) * 64 + ww * 8 + wz;
            rowl[mt][rh] = wm * 64 + mt * 16 + rh * 8 + (lane >> 2);

            float s = 0.f, q = 0.f;
            size_t ob = (size_t)tok[mt][rh] * 256;
#pragma unroll
            for (int nt = 0; nt < 4; nt++) {
                int c = wn * 32 + nt * 8 + (lane & 3) * 2;
                float2 rr = *(const float2*)(x + ob + c);
                float u0 = acc[mt][nt][rh * 2 + 0] + bias[c]     + rr.x;
                float u1 = acc[mt][nt][rh * 2 + 1] + bias[c + 1] + rr.y;
                acc[mt][nt][rh * 2 + 0] = u0;
                acc[mt][nt][rh * 2 + 1] = u1;
                *(__half2*)(y + ob + c) = __floats2half2_rn(u0, u1);
                s += u0 + u1;
                q += u0 * u0 + u1 * u1;
            }
            s += __shfl_xor_sync(0xffffffffu, s, 1);
            s += __shfl_xor_sync(0xffffffffu, s, 2);
            q += __shfl_xor_sync(0xffffffffu, q, 1);
            q += __shfl_xor_sync(0xffffffffu, q, 2);
            if ((lane & 3) == 0) {
                red[rowl[mt][rh] * 16 + wn * 2]     = s;
                red[rowl[mt][rh] * 16 + wn * 2 + 1] = q;
            }
        }
    }
    __syncthreads();

#pragma unroll
    for (int mt = 0; mt < 4; mt++) {
#pragma unroll
        for (int rh = 0; rh < 2; rh++) {
            const float* rp = red + rowl[mt][rh] * 16;
            float S = 0.f, Q = 0.f;
#pragma unroll
            for (int w = 0; w < 8; w++) { S += rp[w * 2]; Q += rp[w * 2 + 1]; }
            float mean = S * (1.f / 256.f);
            float var = Q * (1.f / 256.f) - mean * mean;
            float rstd = rsqrtf(var + 1e-5f);
            size_t ob = (size_t)tok[mt][rh] * 256;
#pragma unroll
            for (int nt = 0; nt < 4; nt++) {
                int c = wn * 32 + nt * 8 + (lane & 3) * 2;
                float h0 = (acc[mt][nt][rh * 2 + 0] - mean) * rstd * lg[c]     + lb[c];
                float h1 = (acc[mt][nt][rh * 2 + 1] - mean) * rstd * lg[c + 1] + lb[c + 1];
                *(__half2*)(xw16 + ob + c) = __floats2half2_rn(h0, h1);
            }
        }
    }
}

// ---------------- windowed attention: one block per (head, window), slice loop ----------------
__global__ __launch_bounds__(256, 2) void attn_mma_kernel(
    const __half* __restrict__ qkv, const float* __restrict__ rpb,
    __half* __restrict__ out)
{
    extern __shared__ char smraw[];
    __half* Qs = (__half*)smraw;            // [256][40]
    __half* Ks = Qs + 256 * 40;             // [256][40]
    __half* Vs = Ks + 256 * 40;             // [256][40]
    float*  Bt  = (float*)(Vs + 256 * 40);  // [7][225], reversed in dw
    float*  Om1 = Bt + 1575;                // [2][4][16][32]
    float*  Ms1 = Om1 + 4096;               // [2][4][16]
    float*  Ss1 = Ms1 + 128;                // [2][4][16]

    const int hh = blockIdx.x, win = blockIdx.y;
    const int tid = threadIdx.x, lane = tid & 31, warp = tid >> 5;
    const int qg = warp & 3, kh = warp >> 2;
    const size_t base = (size_t)win * 256 * QKVDIM;

    if (tid < 225) {
        int dh30 = (tid / 15) * 30;
#pragma unroll
        for (int off = 0; off < 7; off++)
            Bt[off * 225 + tid] = rpb[(off * 225 + dh30 + 14 - tid) * 8 + hh];
    }
#pragma unroll
    for (int r = 0; r < 4; r++) {
        int idx = tid + r * 256;
        int q = idx >> 2, c8 = idx & 3;
        const __half* src = qkv + base + (size_t)q * QKVDIM + hh * 32 + c8 * 8;
        *(uint4*)(Qs + q * 40 + c8 * 8) = *(const uint4*)src;
        *(uint4*)(Ks + q * 40 + c8 * 8) = *(const uint4*)(src + 256);
        *(uint4*)(Vs + q * 40 + c8 * 8) = *(const uint4*)(src + 512);
    }
    __syncthreads();

    const int qrow_l = qg * 16 + (lane >> 2);
    const int hq0 = qrow_l >> 3, wq = qrow_l & 7;
    const int hq1 = (qrow_l + 8) >> 3;
    const int j0 = 2 * (lane & 3) - wq + 7;
    const int base0 = (hq0 + 7) * 15 + j0;
    const int base1 = (hq1 + 7) * 15 + j0;
    const int r0l = lane >> 2;
    const int c2 = 2 * (lane & 3);

#pragma unroll 1
    for (int i = 0; i < 4; i++) {
        const int p = i & 1;
        uint32_t qf[2][4];
#pragma unroll
        for (int ks = 0; ks < 2; ks++) {
            uint32_t ad = smem_u32(Qs + (i * 64 + qg * 16 + (lane & 15)) * 40
                                      + ((lane >> 4) + ks * 2) * 8);
            LDM_X4(qf[ks][0], qf[ks][1], qf[ks][2], qf[ks][3], ad);
        }

        float sacc[12][4];
#pragma unroll
        for (int nb = 0; nb < 12; nb++) {
            sacc[nb][0] = 0.f; sacc[nb][1] = 0.f; sacc[nb][2] = 0.f; sacc[nb][3] = 0.f;
        }
#pragma unroll
        for (int kg = 0; kg < 6; kg++) {
            int c = kh * 96 + kg * 16;
            int gb = (c >= i * 64) ? c + 64 : c;
#pragma unroll
            for (int ks = 0; ks < 2; ks++) {
                uint32_t ad = smem_u32(Ks + (gb + (lane & 7) + ((lane >> 4) << 3)) * 40
                                          + (((lane >> 3) & 1) + ks * 2) * 8);
                uint32_t r0, r1, r2, r3;
                LDM_X4(r0, r1, r2, r3, ad);
                MMA_161608(sacc[kg * 2 + 0], qf[ks][0], qf[ks][1], qf[ks][2], qf[ks][3], r0, r1);
                MMA_161608(sacc[kg * 2 + 1], qf[ks][0], qf[ks][1], qf[ks][2], qf[ks][3], r2, r3);
            }
        }

        float mx0 = -1e30f, mx1 = -1e30f;
#pragma unroll
        for (int nb = 0; nb < 12; nb++) {
            int t12 = kh * 12 + nb;
            int hk15 = (t12 & 7) * 15;
            int kb = t12 * 8;
            int dk = (t12 >> 3) + ((kb >= i * 64) ? 1 : 0);
            const float* bt = Bt + (i - dk + 3) * 225;
            sacc[nb][0] += bt[base0 - hk15];
            sacc[nb][1] += bt[base0 - hk15 + 1];
            sacc[nb][2] += bt[base1 - hk15];
            sacc[nb][3] += bt[base1 - hk15 + 1];
            mx0 = fmaxf(mx0, fmaxf(sacc[nb][0], sacc[nb][1]));
            mx1 = fmaxf(mx1, fmaxf(sacc[nb][2], sacc[nb][3]));
        }
        mx0 = fmaxf(mx0, __shfl_xor_sync(0xffffffffu, mx0, 1));
        mx0 = fmaxf(mx0, __shfl_xor_sync(0xffffffffu, mx0, 2));
        mx1 = fmaxf(mx1, __shfl_xor_sync(0xffffffffu, mx1, 1));
        mx1 = fmaxf(mx1, __shfl_xor_sync(0xffffffffu, mx1, 2));

        float s0 = 0.f, s1 = 0.f;
        uint32_t pf[12][2];
#pragma unroll
        for (int nb = 0; nb < 12; nb++) {
            float e0 = __expf(sacc[nb][0] - mx0);
            float e1 = __expf(sacc[nb][1] - mx0);
            float e2 = __expf(sacc[nb][2] - mx1);
            float e3 = __expf(sacc[nb][3] - mx1);
            s0 += e0 + e1; s1 += e2 + e3;
            __half2 p01 = __floats2half2_rn(e0, e1);
            __half2 p23 = __floats2half2_rn(e2, e3);
            pf[nb][0] = *(uint32_t*)&p01;
            pf[nb][1] = *(uint32_t*)&p23;
        }
        s0 += __shfl_xor_sync(0xffffffffu, s0, 1);
        s0 += __shfl_xor_sync(0xffffffffu, s0, 2);
        s1 += __shfl_xor_sync(0xffffffffu, s1, 1);
        s1 += __shfl_xor_sync(0xffffffffu, s1, 2);

        float oacc[4][4];
#pragma unroll
        for (int nb = 0; nb < 4; nb++) {
            oacc[nb][0] = 0.f; oacc[nb][1] = 0.f; oacc[nb][2] = 0.f; oacc[nb][3] = 0.f;
        }
#pragma unroll
        for (int kt = 0; kt < 6; kt++) {
            int c = kh * 96 + kt * 16;
            int gb = (c >= i * 64) ? c + 64 : c;
            uint32_t a0 = pf[kt * 2][0],     a1 = pf[kt * 2][1];
            uint32_t a2 = pf[kt * 2 + 1][0], a3 = pf[kt * 2 + 1][1];
#pragma unroll
            for (int dh2 = 0; dh2 < 2; dh2++) {
                uint32_t ad = smem_u32(Vs + (gb + (lane & 7) + (((lane >> 3) & 1) << 3)) * 40
                                          + dh2 * 16 + ((lane >> 4) << 3));
                uint32_t v0, v1, v2, v3;
                asm volatile("ldmatrix.sync.aligned.m8n8.x4.trans.shared.b16 {%0,%1,%2,%3}, [%4];"
                             : "=r"(v0), "=r"(v1), "=r"(v2), "=r"(v3) : "r"(ad));
                MMA_161608(oacc[dh2 * 2 + 0], a0, a1, a2, a3, v0, v1);
                MMA_161608(oacc[dh2 * 2 + 1], a0, a1, a2, a3, v2, v3);
            }
        }

        float* Om = Om1 + p * 2048;
        float* Ms = Ms1 + p * 64;
        float* Ss = Ss1 + p * 64;
        if (kh == 1) {
            if ((lane & 3) == 0) {
                Ms[qg * 16 + r0l]     = mx0;  Ss[qg * 16 + r0l]     = s0;
                Ms[qg * 16 + 8 + r0l] = mx1;  Ss[qg * 16 + 8 + r0l] = s1;
            }
            float* om = Om + qg * 512;
#pragma unroll
            for (int nb = 0; nb < 4; nb++) {
                om[r0l * 32 + nb * 8 + c2]           = oacc[nb][0];
                om[r0l * 32 + nb * 8 + c2 + 1]       = oacc[nb][1];
                om[(8 + r0l) * 32 + nb * 8 + c2]     = oacc[nb][2];
                om[(8 + r0l) * 32 + nb * 8 + c2 + 1] = oacc[nb][3];
            }
        }
        __syncthreads();
        if (kh == 0) {
            float mB0 = Ms[qg * 16 + r0l],     sB0 = Ss[qg * 16 + r0l];
            float mB1 = Ms[qg * 16 + 8 + r0l], sB1 = Ss[qg * 16 + 8 + r0l];
            float m0 = fmaxf(mx0, mB0), m1 = fmaxf(mx1, mB1);
            float a0 = __expf(mx0 - m0), b0 = __expf(mB0 - m0);
            float a1 = __expf(mx1 - m1), b1 = __expf(mB1 - m1);
            float inv0 = 1.f / (a0 * s0 + b0 * sB0);
            float inv1 = 1.f / (a1 * s1 + b1 * sB1);
            const float* om = Om + qg * 512;
            size_t o0 = ((size_t)(win * 256 + i * 64 + qrow_l)) * 256 + hh * 32;
#pragma unroll
            for (int nb = 0; nb < 4; nb++) {
                int c = nb * 8 + c2;
                float v0 = (a0 * oacc[nb][0] + b0 * om[r0l * 32 + c])           * inv0;
                float v1 = (a0 * oacc[nb][1] + b0 * om[r0l * 32 + c + 1])       * inv0;
                float v2 = (a1 * oacc[nb][2] + b1 * om[(8 + r0l) * 32 + c])     * inv1;
                float v3 = (a1 * oacc[nb][3] + b1 * om[(8 + r0l) * 32 + c + 1]) * inv1;
                *(__half2*)(out + o0 + c)           = __floats2half2_rn(v0, v1);
                *(__half2*)(out + o0 + 8 * 256 + c) = __floats2half2_rn(v2, v3);
            }
        }
    }
}

// ---------------- launch ----------------
extern "C" void kernel_launch(void* const* d_in, const int* in_sizes, int n_in,
                              void* d_out, int out_size) {
    const float* x     = (const float*)d_in[0];
    const float* ln1_g = (const float*)d_in[1];
    const float* ln1_b = (const float*)d_in[2];
    const float* ln2_g = (const float*)d_in[3];
    const float* ln2_b = (const float*)d_in[4];
    const float* wq    = (const float*)d_in[5];
    const float* wkv   = (const float*)d_in[6];
    const float* wp    = (const float*)d_in[7];
    const float* bp    = (const float*)d_in[8];
    const float* rpb   = (const float*)d_in[9];
    const float* w1    = (const float*)d_in[10];
    const float* b1    = (const float*)d_in[11];
    const float* w2    = (const float*)d_in[12];
    const float* b2    = (const float*)d_in[13];
    float* out = (float*)d_out;

    __half *qkv16, *y16, *xw16, *attn16, *h16, *btq, *btp, *bt1, *bt2;
    cudaGetSymbolAddress((void**)&qkv16,  g_qkv16);
    cudaGetSymbolAddress((void**)&y16,    g_y16);
    cudaGetSymbolAddress((void**)&xw16,   g_xw16);
    cudaGetSymbolAddress((void**)&attn16, g_attn16);
    cudaGetSymbolAddress((void**)&h16,    g_h16);
    cudaGetSymbolAddress((void**)&btq,    g_btq);
    cudaGetSymbolAddress((void**)&btp,    g_btp);
    cudaGetSymbolAddress((void**)&bt1,    g_bt1);
    cudaGetSymbolAddress((void**)&bt2,    g_bt2);

    const int ATTN_SMEM = 61440 + 23708;  // 85148
    cudaFuncSetAttribute(attn_mma_kernel, cudaFuncAttributeMaxDynamicSharedMemorySize, ATTN_SMEM);

    const int GEMM_SMEM = 3 * 32768;      // 98304
    cudaFuncSetAttribute(hmma_gemm<4,256,768>, cudaFuncAttributeMaxDynamicSharedMemorySize, GEMM_SMEM);
    cudaFuncSetAttribute(hmma_gemm<1,256,512>, cudaFuncAttributeMaxDynamicSharedMemorySize, GEMM_SMEM);
    cudaFuncSetAttribute(hmma_gemm<3,512,256>, cudaFuncAttributeMaxDynamicSharedMemorySize, GEMM_SMEM);

    const int PROJ_SMEM = 3 * 49152;      // 147456
    cudaFuncSetAttribute(hmma_proj_ln, cudaFuncAttributeMaxDynamicSharedMemorySize, PROJ_SMEM);

    prep_w_kernel<<<2048, 256>>>(wq, wkv, wp, w1, w2);
    ln16_kernel<true><<<TOKENS / 8, 256>>>(x, ln1_g, ln1_b, xw16);
    hmma_gemm<4,256,768><<<dim3(6, TOKENS / 128), 256, GEMM_SMEM>>>(xw16, btq, nullptr, nullptr, qkv16);
    attn_mma_kernel<<<dim3(8, 512), 256, ATTN_SMEM>>>(qkv16, rpb, attn16);
    hmma_proj_ln<<<TOKENS / 128, 512, PROJ_SMEM>>>(attn16, btp, bp, x, ln2_g, ln2_b, y16, xw16);
    hmma_gemm<1,256,512><<<dim3(4, TOKENS / 128), 256, GEMM_SMEM>>>(xw16, bt1, b1, nullptr, h16);
    hmma_gemm<3,512,256><<<dim3(2, TOKENS / 128), 256, GEMM_SMEM>>>(h16, bt2, b2, y16, out);
}

// round 17
// speedup vs baseline: 1.0780x; 1.0010x over previous
#include <cuda_runtime.h>
#include <cuda_fp16.h>
#include <math.h>
#include <stdint.h>

#define TOKENS   131072
#define CDIM     256
#define QKVDIM   768
#define HIDDIM   512

// ---------------- scratch ----------------
__device__ __half g_qkv16[100663296];  // (131072, 768) fp16
__device__ __half g_y16  [33554432];   // (131072, 256) fp16 residual stream
__device__ __half g_xw16 [33554432];   // (131072, 256) fp16
__device__ __half g_attn16[33554432];  // (131072, 256) fp16 (window layout)
__device__ __half g_h16  [67108864];   // (131072, 512) fp16
__device__ __half g_btq  [196608];     // [768,256]  = [wq*scale | wkv]^T
__device__ __half g_btp  [65536];      // [256,256]  = wp^T
__device__ __half g_bt1  [131072];     // [512,256]  = w1^T
__device__ __half g_bt2  [131072];     // [256,512]  = w2^T

// ---------------- helpers ----------------
__device__ __forceinline__ uint32_t smem_u32(const void* p) {
    uint32_t a;
    asm("{ .reg .u64 t; cvta.to.shared.u64 t, %1; cvt.u32.u64 %0, t; }" : "=r"(a) : "l"(p));
    return a;
}
__device__ __forceinline__ float gelu_exact(float x) {
    return 0.5f * x * (1.0f + erff(x * 0.70710678118654752f));
}
#define MMA_161608(ACC, A0,A1,A2,A3, B0,B1) \
    asm volatile( \
        "mma.sync.aligned.m16n8k16.row.col.f32.f16.f16.f32 " \
        "{%0,%1,%2,%3}, {%4,%5,%6,%7}, {%8,%9}, {%0,%1,%2,%3};" \
        : "+f"((ACC)[0]), "+f"((ACC)[1]), "+f"((ACC)[2]), "+f"((ACC)[3]) \
        : "r"(A0), "r"(A1), "r"(A2), "r"(A3), "r"(B0), "r"(B1))
#define CP_ASYNC16(dst, src) \
    asm volatile("cp.async.cg.shared.global [%0], [%1], 16;" :: "r"(dst), "l"(src))
#define CP_COMMIT() asm volatile("cp.async.commit_group;")
#define CP_WAIT0()  asm volatile("cp.async.wait_group 0;" ::: "memory")
#define LDM_X4(R0,R1,R2,R3,AD) \
    asm volatile("ldmatrix.sync.aligned.m8n8.x4.shared.b16 {%0,%1,%2,%3}, [%4];" \
                 : "=r"(R0), "=r"(R1), "=r"(R2), "=r"(R3) : "r"(AD))

// ---------------- weight prep ----------------
__global__ void prep_w_kernel(const float* __restrict__ wq, const float* __restrict__ wkv,
                              const float* __restrict__ wp, const float* __restrict__ w1,
                              const float* __restrict__ w2) {
    const float scale = 0.17677669529663687f;
    int idx = blockIdx.x * 256 + threadIdx.x;   // 524288 total
    if (idx < 196608) {
        int n = idx / 256, k = idx % 256;
        float v = (n < 256) ? wq[k * 256 + n] * scale : wkv[k * 512 + (n - 256)];
        g_btq[idx] = __float2half_rn(v);
    } else if (idx < 262144) {
        int loc = idx - 196608;
        int n = loc / 256, k = loc % 256;
        g_btp[loc] = __float2half_rn(wp[k * 256 + n]);
    } else if (idx < 393216) {
        int loc = idx - 262144;
        int n = loc / 256, k = loc % 256;
        g_bt1[loc] = __float2half_rn(w1[k * 512 + n]);
    } else {
        int loc = idx - 393216;
        int n = loc / 512, k = loc % 512;
        g_bt2[loc] = __float2half_rn(w2[k * 256 + n]);
    }
}

// ---------------- LayerNorm -> fp16 (LN1) ----------------
template <bool PART>
__global__ void ln16_kernel(const float* __restrict__ x, const float* __restrict__ g,
                            const float* __restrict__ b, __half* __restrict__ out) {
    int warp = threadIdx.x >> 5, lane = threadIdx.x & 31;
    int t = blockIdx.x * 8 + warp;
    const float* row = x + (size_t)t * CDIM;

    float4 v0 = *(const float4*)(row + lane * 8);
    float4 v1 = *(const float4*)(row + lane * 8 + 4);

    float s = v0.x + v0.y + v0.z + v0.w + v1.x + v1.y + v1.z + v1.w;
#pragma unroll
    for (int o = 16; o; o >>= 1) s += __shfl_xor_sync(0xffffffffu, s, o);
    float mean = s * (1.f / 256.f);

    float d0x = v0.x - mean, d0y = v0.y - mean, d0z = v0.z - mean, d0w = v0.w - mean;
    float d1x = v1.x - mean, d1y = v1.y - mean, d1z = v1.z - mean, d1w = v1.w - mean;
    float vs = d0x*d0x + d0y*d0y + d0z*d0z + d0w*d0w + d1x*d1x + d1y*d1y + d1z*d1z + d1w*d1w;
#pragma unroll
    for (int o = 16; o; o >>= 1) vs += __shfl_xor_sync(0xffffffffu, vs, o);
    float rstd = rsqrtf(vs * (1.f / 256.f) + 1e-5f);

    size_t orow;
    if (PART) {
        int w = t & 63, h = (t >> 6) & 63, d = (t >> 12) & 3, bb = t >> 14;
        int win = (bb * 8 + (h >> 3)) * 8 + (w >> 3);
        int n   = d * 64 + (h & 7) * 8 + (w & 7);
        orow = (size_t)(win * 256 + n) * CDIM;
    } else {
        orow = (size_t)t * CDIM;
    }

    float4 g0 = *(const float4*)(g + lane * 8);
    float4 g1 = *(const float4*)(g + lane * 8 + 4);
    float4 b0 = *(const float4*)(b + lane * 8);
    float4 b1 = *(const float4*)(b + lane * 8 + 4);

    __half2 h0 = __floats2half2_rn(d0x * rstd * g0.x + b0.x, d0y * rstd * g0.y + b0.y);
    __half2 h1 = __floats2half2_rn(d0z * rstd * g0.z + b0.z, d0w * rstd * g0.w + b0.w);
    __half2 h2 = __floats2half2_rn(d1x * rstd * g1.x + b1.x, d1y * rstd * g1.y + b1.y);
    __half2 h3 = __floats2half2_rn(d1z * rstd * g1.z + b1.z, d1w * rstd * g1.w + b1.w);
    uint4 u;
    u.x = *(uint32_t*)&h0; u.y = *(uint32_t*)&h1; u.z = *(uint32_t*)&h2; u.w = *(uint32_t*)&h3;
    *(uint4*)&out[orow + lane * 8] = u;
}

// ---------------- HMMA GEMM with 3-stage cp.async ring ----------------
// MODE 1: gelu(+bias)->fp16 (smem-staged coalesced stores).
// MODE 3: +bias + fp16 res -> fp32. MODE 4: fp16 out, no bias (smem-staged).
template <int MODE, int KDIM, int NGLOB>
__global__ __launch_bounds__(256, 2) void hmma_gemm(
    const __half* __restrict__ A, const __half* __restrict__ BT,
    const float* __restrict__ bias, const void* __restrict__ resv,
    void* __restrict__ outv)
{
    extern __shared__ __align__(128) char smring[];

    const int tid = threadIdx.x, lane = tid & 31, wid = tid >> 5;
    const int wm = wid >> 2, wn = wid & 3;
    const int tileM = blockIdx.y << 7, tileN = blockIdx.x << 7;
    const uint32_t sbase = smem_u32(smring);

    const int sr = tid >> 3, scb = tid & 7;
    const uint32_t soff0 = ((uint32_t)(sr * 128 + scb * 16));

    constexpr int NCHUNK = KDIM / 64;

    float acc[4][4][4];
#pragma unroll
    for (int mt = 0; mt < 4; mt++)
#pragma unroll
        for (int nt = 0; nt < 4; nt++)
#pragma unroll
            for (int j = 0; j < 4; j++) acc[mt][nt][j] = 0.f;

    auto stage = [&](int k0, int s) {
        uint32_t ab = sbase + s * 32768, bb = ab + 16384;
#pragma unroll
        for (int it = 0; it < 4; it++) {
            int r = sr + it * 32;
            uint32_t off = soff0 + it * 32 * 128;
            uint32_t d = ab + (off ^ ((off >> 3) & 0x70));
            CP_ASYNC16(d, A + (size_t)(tileM + r) * KDIM + k0 + scb * 8);
        }
#pragma unroll
        for (int it = 0; it < 4; it++) {
            int r = sr + it * 32;
            uint32_t off = soff0 + it * 32 * 128;
            uint32_t d = bb + (off ^ ((off >> 3) & 0x70));
            CP_ASYNC16(d, BT + (size_t)(tileN + r) * KDIM + k0 + scb * 8);
        }
    };

    stage(0, 0);
    CP_COMMIT();
    if (NCHUNK > 1) { stage(64, 1); CP_COMMIT(); }

    int sbuf = 0, snext = (NCHUNK > 1) ? 2 : 1;
#pragma unroll 1
    for (int ch = 0; ch < NCHUNK; ch++) {
        if (ch + 1 < NCHUNK) {
            asm volatile("cp.async.wait_group 1;" ::: "memory");
        } else {
            CP_WAIT0();
        }
        __syncthreads();
        if (ch + 2 < NCHUNK) {
            stage((ch + 2) * 64, snext);
            CP_COMMIT();
            snext = (snext == 2) ? 0 : snext + 1;
        }

        const uint32_t ab = sbase + sbuf * 32768, bb = ab + 16384;
#pragma unroll
        for (int ks = 0; ks < 4; ks++) {
            uint32_t bf[4][2];
#pragma unroll
            for (int bp = 0; bp < 2; bp++) {
                int nrow = wn * 32 + bp * 16 + (lane & 7) + ((lane >> 4) << 3);
                int kcol = ks * 16 + (((lane >> 3) & 1) << 3);
                uint32_t off = nrow * 128 + (kcol >> 3) * 16;
                uint32_t ad = bb + (off ^ ((off >> 3) & 0x70));
                uint32_t r0, r1, r2, r3;
                LDM_X4(r0, r1, r2, r3, ad);
                bf[bp * 2 + 0][0] = r0; bf[bp * 2 + 0][1] = r1;
                bf[bp * 2 + 1][0] = r2; bf[bp * 2 + 1][1] = r3;
            }
#pragma unroll
            for (int mt = 0; mt < 4; mt++) {
                int mrow = wm * 64 + mt * 16 + (lane & 15);
                int kcol = ks * 16 + ((lane >> 4) << 3);
                uint32_t off = mrow * 128 + (kcol >> 3) * 16;
                uint32_t ad = ab + (off ^ ((off >> 3) & 0x70));
                uint32_t a0, a1, a2, a3;
                LDM_X4(a0, a1, a2, a3, ad);
#pragma unroll
                for (int nt = 0; nt < 4; nt++)
                    MMA_161608(acc[mt][nt], a0, a1, a2, a3, bf[nt][0], bf[nt][1]);
            }
        }
        sbuf = (sbuf == 2) ? 0 : sbuf + 1;
    }

    if (MODE == 3) {
#pragma unroll
        for (int mt = 0; mt < 4; mt++) {
#pragma unroll
            for (int rh = 0; rh < 2; rh++) {
                int m = tileM + wm * 64 + mt * 16 + rh * 8 + (lane >> 2);
                size_t obase = (size_t)m * NGLOB;
#pragma unroll
                for (int nt = 0; nt < 4; nt++) {
                    int c = tileN + wn * 32 + nt * 8 + (lane & 3) * 2;
                    __half2 rr16 = *(const __half2*)((const __half*)resv + obase + c);
                    float2 rr = __half22float2(rr16);
                    *(float2*)((float*)outv + obase + c) =
                        make_float2(acc[mt][nt][rh * 2 + 0] + bias[c] + rr.x,
                                    acc[mt][nt][rh * 2 + 1] + bias[c + 1] + rr.y);
                }
            }
        }
    } else {
        // fp16 path: stage through smem, emit coalesced 16B stores
        __syncthreads();
        __half* tile = (__half*)smring;
        const int TS = 136;
#pragma unroll
        for (int mt = 0; mt < 4; mt++) {
#pragma unroll
            for (int rh = 0; rh < 2; rh++) {
                int rowl = wm * 64 + mt * 16 + rh * 8 + (lane >> 2);
#pragma unroll
                for (int nt = 0; nt < 4; nt++) {
                    int c = wn * 32 + nt * 8 + (lane & 3) * 2;
                    float v0 = acc[mt][nt][rh * 2 + 0];
                    float v1 = acc[mt][nt][rh * 2 + 1];
                    if (MODE == 1) {
                        v0 = gelu_exact(v0 + bias[tileN + c]);
                        v1 = gelu_exact(v1 + bias[tileN + c + 1]);
                    }
                    *(__half2*)&tile[rowl * TS + c] = __floats2half2_rn(v0, v1);
                }
            }
        }
        __syncthreads();
#pragma unroll
        for (int it = 0; it < 8; it++) {
            int linear = tid + it * 256;
            int row = linear >> 4, c16 = (linear & 15) * 8;
            uint4 v = *(uint4*)&tile[row * TS + c16];
            *(uint4*)((__half*)outv + (size_t)(tileM + row) * NGLOB + tileN + c16) = v;
        }
    }
}

// ---------------- fused proj GEMM + residual + reverse-scatter + LayerNorm2 ----------------
// y is emitted fp16 (residual stream); LN2 uses fp32 registers before rounding.
__global__ __launch_bounds__(512, 1) void hmma_proj_ln(
    const __half* __restrict__ A, const __half* __restrict__ BT,
    const float* __restrict__ bias, const float* __restrict__ x,
    const float* __restrict__ lg, const float* __restrict__ lb,
    __half* __restrict__ y, __half* __restrict__ xw16)
{
    extern __shared__ __align__(128) char smring[];

    const int tid = threadIdx.x, lane = tid & 31, wid = tid >> 5;
    const int wm = wid >> 3, wn = wid & 7;
    const int tileM = blockIdx.x << 7;
    const uint32_t sbase = smem_u32(smring);
    constexpr int KDIM = 256;
    constexpr int NCHUNK = 4;

    const int sr8 = tid >> 3, scb = tid & 7;

    float acc[4][4][4];
#pragma unroll
    for (int mt = 0; mt < 4; mt++)
#pragma unroll
        for (int nt = 0; nt < 4; nt++)
#pragma unroll
            for (int j = 0; j < 4; j++) acc[mt][nt][j] = 0.f;

    auto stage = [&](int k0, int s) {
        uint32_t ab = sbase + s * 49152, bb = ab + 16384;
#pragma unroll
        for (int it = 0; it < 2; it++) {
            int r = sr8 + it * 64;
            uint32_t off = (uint32_t)(r * 128 + scb * 16);
            uint32_t d = ab + (off ^ ((off >> 3) & 0x70));
            CP_ASYNC16(d, A + (size_t)(tileM + r) * KDIM + k0 + scb * 8);
        }
#pragma unroll
        for (int it = 0; it < 4; it++) {
            int r = sr8 + it * 64;
            uint32_t off = (uint32_t)(r * 128 + scb * 16);
            uint32_t d = bb + (off ^ ((off >> 3) & 0x70));
            CP_ASYNC16(d, BT + (size_t)r * KDIM + k0 + scb * 8);
        }
    };

    stage(0, 0);
    CP_COMMIT();
    stage(64, 1);
    CP_COMMIT();

    int sbuf = 0, snext = 2;
#pragma unroll 1
    for (int ch = 0; ch < NCHUNK; ch++) {
        if (ch + 1 < NCHUNK) {
            asm volatile("cp.async.wait_group 1;" ::: "memory");
        } else {
            CP_WAIT0();
        }
        __syncthreads();
        if (ch + 2 < NCHUNK) {
            stage((ch + 2) * 64, snext);
            CP_COMMIT();
            snext = (snext == 2) ? 0 : snext + 1;
        }

        const uint32_t ab = sbase + sbuf * 49152, bb = ab + 16384;
#pragma unroll
        for (int ks = 0; ks < 4; ks++) {
            uint32_t bf[4][2];
#pragma unroll
            for (int bp = 0; bp < 2; bp++) {
                int nrow = wn * 32 + bp * 16 + (lane & 7) + ((lane >> 4) << 3);
                int kcol = ks * 16 + (((lane >> 3) & 1) << 3);
                uint32_t off = nrow * 128 + (kcol >> 3) * 16;
                uint32_t ad = bb + (off ^ ((off >> 3) & 0x70));
                uint32_t r0, r1, r2, r3;
                LDM_X4(r0, r1, r2, r3, ad);
                bf[bp * 2 + 0][0] = r0; bf[bp * 2 + 0][1] = r1;
                bf[bp * 2 + 1][0] = r2; bf[bp * 2 + 1][1] = r3;
            }
#pragma unroll
            for (int mt = 0; mt < 4; mt++) {
                int mrow = wm * 64 + mt * 16 + (lane & 15);
                int kcol = ks * 16 + ((lane >> 4) << 3);
                uint32_t off = mrow * 128 + (kcol >> 3) * 16;
                uint32_t ad = ab + (off ^ ((off >> 3) & 0x70));
                uint32_t a0, a1, a2, a3;
                LDM_X4(a0, a1, a2, a3, ad);
#pragma unroll
                for (int nt = 0; nt < 4; nt++)
                    MMA_161608(acc[mt][nt], a0, a1, a2, a3, bf[nt][0], bf[nt][1]);
            }
        }
        sbuf = (sbuf == 2) ? 0 : sbuf + 1;
    }

    __syncthreads();
    float* red = (float*)smring;

    int tok[4][2];
    int rowl[4][2];
#pragma unroll
    for (int mt = 0; mt < 4; mt++) {
#pragma unroll
        for (int rh = 0; rh < 2; rh++) {
            int m = tileM + wm * 64 + mt * 16 + rh * 8 + (lane >> 2);
            int win = m >> 8, n = m & 255;
            int bb_ = win >> 6, hw = (win >> 3) & 7, ww = win & 7;
            int dz = n >> 6, hz = (n >> 3) & 7, wz = n & 7;
            tok[mt][rh] = ((bb_ * 4 + dz) * 64 + hw * 8 + hz) * 64 + ww * 8 + wz;
            rowl[mt][rh] = wm * 64 + mt * 16 + rh * 8 + (lane >> 2);

            float s = 0.f, q = 0.f;
            size_t ob = (size_t)tok[mt][rh] * 256;
#pragma unroll
            for (int nt = 0; nt < 4; nt++) {
                int c = wn * 32 + nt * 8 + (lane & 3) * 2;
                float2 rr = *(const float2*)(x + ob + c);
                float u0 = acc[mt][nt][rh * 2 + 0] + bias[c]     + rr.x;
                float u1 = acc[mt][nt][rh * 2 + 1] + bias[c + 1] + rr.y;
                acc[mt][nt][rh * 2 + 0] = u0;
                acc[mt][nt][rh * 2 + 1] = u1;
                *(__half2*)(y + ob + c) = __floats2half2_rn(u0, u1);
                s += u0 + u1;
                q += u0 * u0 + u1 * u1;
            }
            s += __shfl_xor_sync(0xffffffffu, s, 1);
            s += __shfl_xor_sync(0xffffffffu, s, 2);
            q += __shfl_xor_sync(0xffffffffu, q, 1);
            q += __shfl_xor_sync(0xffffffffu, q, 2);
            if ((lane & 3) == 0) {
                red[rowl[mt][rh] * 16 + wn * 2]     = s;
                red[rowl[mt][rh] * 16 + wn * 2 + 1] = q;
            }
        }
    }
    __syncthreads();

#pragma unroll
    for (int mt = 0; mt < 4; mt++) {
#pragma unroll
        for (int rh = 0; rh < 2; rh++) {
            const float* rp = red + rowl[mt][rh] * 16;
            float S = 0.f, Q = 0.f;
#pragma unroll
            for (int w = 0; w < 8; w++) { S += rp[w * 2]; Q += rp[w * 2 + 1]; }
            float mean = S * (1.f / 256.f);
            float var = Q * (1.f / 256.f) - mean * mean;
            float rstd = rsqrtf(var + 1e-5f);
            size_t ob = (size_t)tok[mt][rh] * 256;
#pragma unroll
            for (int nt = 0; nt < 4; nt++) {
                int c = wn * 32 + nt * 8 + (lane & 3) * 2;
                float h0 = (acc[mt][nt][rh * 2 + 0] - mean) * rstd * lg[c]     + lb[c];
                float h1 = (acc[mt][nt][rh * 2 + 1] - mean) * rstd * lg[c + 1] + lb[c + 1];
                *(__half2*)(xw16 + ob + c) = __floats2half2_rn(h0, h1);
            }
        }
    }
}

// ---------------- windowed attention: one block per (head, window), slice loop ----------------
__global__ __launch_bounds__(256, 2) void attn_mma_kernel(
    const __half* __restrict__ qkv, const float* __restrict__ rpb,
    __half* __restrict__ out)
{
    extern __shared__ char smraw[];
    __half* Qs = (__half*)smraw;            // [256][40]
    __half* Ks = Qs + 256 * 40;             // [256][40]
    __half* Vs = Ks + 256 * 40;             // [256][40]
    float*  Bt  = (float*)(Vs + 256 * 40);  // [7][225], reversed in dw
    float*  Om1 = Bt + 1575;                // [2][4][16][32]
    float*  Ms1 = Om1 + 4096;               // [2][4][16]
    float*  Ss1 = Ms1 + 128;                // [2][4][16]

    const int hh = blockIdx.x, win = blockIdx.y;
    const int tid = threadIdx.x, lane = tid & 31, warp = tid >> 5;
    const int qg = warp & 3, kh = warp >> 2;
    const size_t base = (size_t)win * 256 * QKVDIM;

    if (tid < 225) {
        int dh30 = (tid / 15) * 30;
#pragma unroll
        for (int off = 0; off < 7; off++)
            Bt[off * 225 + tid] = rpb[(off * 225 + dh30 + 14 - tid) * 8 + hh];
    }
#pragma unroll
    for (int r = 0; r < 4; r++) {
        int idx = tid + r * 256;
        int q = idx >> 2, c8 = idx & 3;
        const __half* src = qkv + base + (size_t)q * QKVDIM + hh * 32 + c8 * 8;
        *(uint4*)(Qs + q * 40 + c8 * 8) = *(const uint4*)src;
        *(uint4*)(Ks + q * 40 + c8 * 8) = *(const uint4*)(src + 256);
        *(uint4*)(Vs + q * 40 + c8 * 8) = *(const uint4*)(src + 512);
    }
    __syncthreads();

    const int qrow_l = qg * 16 + (lane >> 2);
    const int hq0 = qrow_l >> 3, wq = qrow_l & 7;
    const int hq1 = (qrow_l + 8) >> 3;
    const int j0 = 2 * (lane & 3) - wq + 7;
    const int base0 = (hq0 + 7) * 15 + j0;
    const int base1 = (hq1 + 7) * 15 + j0;
    const int r0l = lane >> 2;
    const int c2 = 2 * (lane & 3);

#pragma unroll 1
    for (int i = 0; i < 4; i++) {
        const int p = i & 1;
        uint32_t qf[2][4];
#pragma unroll
        for (int ks = 0; ks < 2; ks++) {
            uint32_t ad = smem_u32(Qs + (i * 64 + qg * 16 + (lane & 15)) * 40
                                      + ((lane >> 4) + ks * 2) * 8);
            LDM_X4(qf[ks][0], qf[ks][1], qf[ks][2], qf[ks][3], ad);
        }

        float sacc[12][4];
#pragma unroll
        for (int nb = 0; nb < 12; nb++) {
            sacc[nb][0] = 0.f; sacc[nb][1] = 0.f; sacc[nb][2] = 0.f; sacc[nb][3] = 0.f;
        }
#pragma unroll
        for (int kg = 0; kg < 6; kg++) {
            int c = kh * 96 + kg * 16;
            int gb = (c >= i * 64) ? c + 64 : c;
#pragma unroll
            for (int ks = 0; ks < 2; ks++) {
                uint32_t ad = smem_u32(Ks + (gb + (lane & 7) + ((lane >> 4) << 3)) * 40
                                          + (((lane >> 3) & 1) + ks * 2) * 8);
                uint32_t r0, r1, r2, r3;
                LDM_X4(r0, r1, r2, r3, ad);
                MMA_161608(sacc[kg * 2 + 0], qf[ks][0], qf[ks][1], qf[ks][2], qf[ks][3], r0, r1);
                MMA_161608(sacc[kg * 2 + 1], qf[ks][0], qf[ks][1], qf[ks][2], qf[ks][3], r2, r3);
            }
        }

        float mx0 = -1e30f, mx1 = -1e30f;
#pragma unroll
        for (int nb = 0; nb < 12; nb++) {
            int t12 = kh * 12 + nb;
            int hk15 = (t12 & 7) * 15;
            int kb = t12 * 8;
            int dk = (t12 >> 3) + ((kb >= i * 64) ? 1 : 0);
            const float* bt = Bt + (i - dk + 3) * 225;
            sacc[nb][0] += bt[base0 - hk15];
            sacc[nb][1] += bt[base0 - hk15 + 1];
            sacc[nb][2] += bt[base1 - hk15];
            sacc[nb][3] += bt[base1 - hk15 + 1];
            mx0 = fmaxf(mx0, fmaxf(sacc[nb][0], sacc[nb][1]));
            mx1 = fmaxf(mx1, fmaxf(sacc[nb][2], sacc[nb][3]));
        }
        mx0 = fmaxf(mx0, __shfl_xor_sync(0xffffffffu, mx0, 1));
        mx0 = fmaxf(mx0, __shfl_xor_sync(0xffffffffu, mx0, 2));
        mx1 = fmaxf(mx1, __shfl_xor_sync(0xffffffffu, mx1, 1));
        mx1 = fmaxf(mx1, __shfl_xor_sync(0xffffffffu, mx1, 2));

        float s0 = 0.f, s1 = 0.f;
        uint32_t pf[12][2];
#pragma unroll
        for (int nb = 0; nb < 12; nb++) {
            float e0 = __expf(sacc[nb][0] - mx0);
            float e1 = __expf(sacc[nb][1] - mx0);
            float e2 = __expf(sacc[nb][2] - mx1);
            float e3 = __expf(sacc[nb][3] - mx1);
            s0 += e0 + e1; s1 += e2 + e3;
            __half2 p01 = __floats2half2_rn(e0, e1);
            __half2 p23 = __floats2half2_rn(e2, e3);
            pf[nb][0] = *(uint32_t*)&p01;
            pf[nb][1] = *(uint32_t*)&p23;
        }
        s0 += __shfl_xor_sync(0xffffffffu, s0, 1);
        s0 += __shfl_xor_sync(0xffffffffu, s0, 2);
        s1 += __shfl_xor_sync(0xffffffffu, s1, 1);
        s1 += __shfl_xor_sync(0xffffffffu, s1, 2);

        float oacc[4][4];
#pragma unroll
        for (int nb = 0; nb < 4; nb++) {
            oacc[nb][0] = 0.f; oacc[nb][1] = 0.f; oacc[nb][2] = 0.f; oacc[nb][3] = 0.f;
        }
#pragma unroll
        for (int kt = 0; kt < 6; kt++) {
            int c = kh * 96 + kt * 16;
            int gb = (c >= i * 64) ? c + 64 : c;
            uint32_t a0 = pf[kt * 2][0],     a1 = pf[kt * 2][1];
            uint32_t a2 = pf[kt * 2 + 1][0], a3 = pf[kt * 2 + 1][1];
#pragma unroll
            for (int dh2 = 0; dh2 < 2; dh2++) {
                uint32_t ad = smem_u32(Vs + (gb + (lane & 7) + (((lane >> 3) & 1) << 3)) * 40
                                          + dh2 * 16 + ((lane >> 4) << 3));
                uint32_t v0, v1, v2, v3;
                asm volatile("ldmatrix.sync.aligned.m8n8.x4.trans.shared.b16 {%0,%1,%2,%3}, [%4];"
                             : "=r"(v0), "=r"(v1), "=r"(v2), "=r"(v3) : "r"(ad));
                MMA_161608(oacc[dh2 * 2 + 0], a0, a1, a2, a3, v0, v1);
                MMA_161608(oacc[dh2 * 2 + 1], a0, a1, a2, a3, v2, v3);
            }
        }

        float* Om = Om1 + p * 2048;
        float* Ms = Ms1 + p * 64;
        float* Ss = Ss1 + p * 64;
        if (kh == 1) {
            if ((lane & 3) == 0) {
                Ms[qg * 16 + r0l]     = mx0;  Ss[qg * 16 + r0l]     = s0;
                Ms[qg * 16 + 8 + r0l] = mx1;  Ss[qg * 16 + 8 + r0l] = s1;
            }
            float* om = Om + qg * 512;
#pragma unroll
            for (int nb = 0; nb < 4; nb++) {
                om[r0l * 32 + nb * 8 + c2]           = oacc[nb][0];
                om[r0l * 32 + nb * 8 + c2 + 1]       = oacc[nb][1];
                om[(8 + r0l) * 32 + nb * 8 + c2]     = oacc[nb][2];
                om[(8 + r0l) * 32 + nb * 8 + c2 + 1] = oacc[nb][3];
            }
        }
        __syncthreads();
        if (kh == 0) {
            float mB0 = Ms[qg * 16 + r0l],     sB0 = Ss[qg * 16 + r0l];
            float mB1 = Ms[qg * 16 + 8 + r0l], sB1 = Ss[qg * 16 + 8 + r0l];
            float m0 = fmaxf(mx0, mB0), m1 = fmaxf(mx1, mB1);
            float a0 = __expf(mx0 - m0), b0 = __expf(mB0 - m0);
            float a1 = __expf(mx1 - m1), b1 = __expf(mB1 - m1);
            float inv0 = 1.f / (a0 * s0 + b0 * sB0);
            float inv1 = 1.f / (a1 * s1 + b1 * sB1);
            const float* om = Om + qg * 512;
            size_t o0 = ((size_t)(win * 256 + i * 64 + qrow_l)) * 256 + hh * 32;
#pragma unroll
            for (int nb = 0; nb < 4; nb++) {
                int c = nb * 8 + c2;
                float v0 = (a0 * oacc[nb][0] + b0 * om[r0l * 32 + c])           * inv0;
                float v1 = (a0 * oacc[nb][1] + b0 * om[r0l * 32 + c + 1])       * inv0;
                float v2 = (a1 * oacc[nb][2] + b1 * om[(8 + r0l) * 32 + c])     * inv1;
                float v3 = (a1 * oacc[nb][3] + b1 * om[(8 + r0l) * 32 + c + 1]) * inv1;
                *(__half2*)(out + o0 + c)           = __floats2half2_rn(v0, v1);
                *(__half2*)(out + o0 + 8 * 256 + c) = __floats2half2_rn(v2, v3);
            }
        }
    }
}

// ---------------- launch ----------------
extern "C" void kernel_launch(void* const* d_in, const int* in_sizes, int n_in,
                              void* d_out, int out_size) {
    const float* x     = (const float*)d_in[0];
    const float* ln1_g = (const float*)d_in[1];
    const float* ln1_b = (const float*)d_in[2];
    const float* ln2_g = (const float*)d_in[3];
    const float* ln2_b = (const float*)d_in[4];
    const float* wq    = (const float*)d_in[5];
    const float* wkv   = (const float*)d_in[6];
    const float* wp    = (const float*)d_in[7];
    const float* bp    = (const float*)d_in[8];
    const float* rpb   = (const float*)d_in[9];
    const float* w1    = (const float*)d_in[10];
    const float* b1    = (const float*)d_in[11];
    const float* w2    = (const float*)d_in[12];
    const float* b2    = (const float*)d_in[13];
    float* out = (float*)d_out;

    __half *qkv16, *y16, *xw16, *attn16, *h16, *btq, *btp, *bt1, *bt2;
    cudaGetSymbolAddress((void**)&qkv16,  g_qkv16);
    cudaGetSymbolAddress((void**)&y16,    g_y16);
    cudaGetSymbolAddress((void**)&xw16,   g_xw16);
    cudaGetSymbolAddress((void**)&attn16, g_attn16);
    cudaGetSymbolAddress((void**)&h16,    g_h16);
    cudaGetSymbolAddress((void**)&btq,    g_btq);
    cudaGetSymbolAddress((void**)&btp,    g_btp);
    cudaGetSymbolAddress((void**)&bt1,    g_bt1);
    cudaGetSymbolAddress((void**)&bt2,    g_bt2);

    const int ATTN_SMEM = 61440 + 23708;  // 85148
    cudaFuncSetAttribute(attn_mma_kernel, cudaFuncAttributeMaxDynamicSharedMemorySize, ATTN_SMEM);

    const int GEMM_SMEM = 3 * 32768;      // 98304
    cudaFuncSetAttribute(hmma_gemm<4,256,768>, cudaFuncAttributeMaxDynamicSharedMemorySize, GEMM_SMEM);
    cudaFuncSetAttribute(hmma_gemm<1,256,512>, cudaFuncAttributeMaxDynamicSharedMemorySize, GEMM_SMEM);
    cudaFuncSetAttribute(hmma_gemm<3,512,256>, cudaFuncAttributeMaxDynamicSharedMemorySize, GEMM_SMEM);

    const int PROJ_SMEM = 3 * 49152;      // 147456
    cudaFuncSetAttribute(hmma_proj_ln, cudaFuncAttributeMaxDynamicSharedMemorySize, PROJ_SMEM);

    prep_w_kernel<<<2048, 256>>>(wq, wkv, wp, w1, w2);
    ln16_kernel<true><<<TOKENS / 8, 256>>>(x, ln1_g, ln1_b, xw16);
    hmma_gemm<4,256,768><<<dim3(6, TOKENS / 128), 256, GEMM_SMEM>>>(xw16, btq, nullptr, nullptr, qkv16);
    attn_mma_kernel<<<dim3(8, 512), 256, ATTN_SMEM>>>(qkv16, rpb, attn16);
    hmma_proj_ln<<<TOKENS / 128, 512, PROJ_SMEM>>>(attn16, btp, bp, x, ln2_g, ln2_b, y16, xw16);
    hmma_gemm<1,256,512><<<dim3(4, TOKENS / 128), 256, GEMM_SMEM>>>(xw16, bt1, b1, nullptr, h16);
    hmma_gemm<3,512,256><<<dim3(2, TOKENS / 128), 256, GEMM_SMEM>>>(h16, bt2, b2, y16, out);
}